// round 1
// baseline (speedup 1.0000x reference)
#include <cuda_runtime.h>
#include <math.h>

#define THREADS 256
#define TILE 32
#define HSTR 132   // hidden smem row stride (128 + 4 pad, float4-aligned)

// Scratch (no allocations allowed): message aggregation buffer + world sum.
__device__ float g_magg[50048 * 64];
__device__ float g_wsum[64];

// ---------------------------------------------------------------------------
// Weight chunk loader: stages 8 rows x HT cols of W into smem, zero-padded
// past KIN. Coalesced across 256 threads.
// ---------------------------------------------------------------------------
__device__ __forceinline__ void load_chunk_w(const float* __restrict__ W, float* wb,
                                             int kbase, int KIN, int HT, int t) {
    const int total = 8 * HT;
    for (int idx = t; idx < total; idx += THREADS) {
        int kk = idx / HT;
        int h  = idx - kk * HT;
        int k  = kbase + kk;
        wb[idx] = (k < KIN) ? W[k * HT + h] : 0.0f;
    }
}

// ---------------------------------------------------------------------------
// GEMM1: hid[32][128] = relu(inp[32][KIN] @ W1[KIN][128] + b1)
// Thread layout: eg = t/64 (4 groups x 8 rows), hg = t%64 (2 cols each).
// Activations read as broadcast float4 from smem; weights double-buffered.
// ---------------------------------------------------------------------------
__device__ __forceinline__ void gemm1_128(const float* __restrict__ W1,
                                          const float* __restrict__ b1,
                                          int KIN, int KPAD,
                                          const float* inp_s, int istride,
                                          float* hid_s, float* wbuf, int t) {
    const int hg = t & 63, eg = t >> 6;
    const int j0 = hg * 2, e0 = eg * 8;
    float acc0[8], acc1[8];
#pragma unroll
    for (int i = 0; i < 8; i++) { acc0[i] = 0.f; acc1[i] = 0.f; }

    const int nc = KPAD >> 3;
    load_chunk_w(W1, wbuf, 0, KIN, 128, t);
    __syncthreads();
    for (int c = 0; c < nc; c++) {
        if (c + 1 < nc)
            load_chunk_w(W1, wbuf + ((c + 1) & 1) * 1024, (c + 1) * 8, KIN, 128, t);
        const float* wb = wbuf + (c & 1) * 1024;
        const int kbase = c * 8;
#pragma unroll
        for (int kq = 0; kq < 2; kq++) {
            float4 a4[8];
#pragma unroll
            for (int i = 0; i < 8; i++)
                a4[i] = *(const float4*)(inp_s + (e0 + i) * istride + kbase + kq * 4);
#pragma unroll
            for (int kk = 0; kk < 4; kk++) {
                float2 w = *(const float2*)(wb + (kq * 4 + kk) * 128 + j0);
#pragma unroll
                for (int i = 0; i < 8; i++) {
                    float a = (kk == 0) ? a4[i].x : (kk == 1) ? a4[i].y
                            : (kk == 2) ? a4[i].z : a4[i].w;
                    acc0[i] = fmaf(a, w.x, acc0[i]);
                    acc1[i] = fmaf(a, w.y, acc1[i]);
                }
            }
        }
        __syncthreads();
    }
    const float bv0 = b1[j0], bv1 = b1[j0 + 1];
#pragma unroll
    for (int i = 0; i < 8; i++) {
        float2 v;
        v.x = fmaxf(acc0[i] + bv0, 0.f);
        v.y = fmaxf(acc1[i] + bv1, 0.f);
        *(float2*)(hid_s + (e0 + i) * HSTR + j0) = v;
    }
    __syncthreads();
}

// ---------------------------------------------------------------------------
// GEMM2: out[32][64] = hid[32][128] @ W2[128][64]  (bias added by caller)
// Thread layout: eg = t/64 (8 rows each), j = t%64 (1 col).
// ---------------------------------------------------------------------------
__device__ __forceinline__ void gemm2_64(const float* __restrict__ W2,
                                         const float* hid_s, float* wbuf, int t,
                                         float acc[8]) {
    const int j = t & 63, eg = t >> 6, e0 = eg * 8;
#pragma unroll
    for (int i = 0; i < 8; i++) acc[i] = 0.f;

    load_chunk_w(W2, wbuf, 0, 128, 64, t);
    __syncthreads();
    for (int c = 0; c < 16; c++) {
        if (c + 1 < 16)
            load_chunk_w(W2, wbuf + ((c + 1) & 1) * 512, (c + 1) * 8, 128, 64, t);
        const float* wb = wbuf + (c & 1) * 512;
        const int kbase = c * 8;
#pragma unroll
        for (int kq = 0; kq < 2; kq++) {
            float4 a4[8];
#pragma unroll
            for (int i = 0; i < 8; i++)
                a4[i] = *(const float4*)(hid_s + (e0 + i) * HSTR + kbase + kq * 4);
#pragma unroll
            for (int kk = 0; kk < 4; kk++) {
                float w = wb[(kq * 4 + kk) * 64 + j];
#pragma unroll
                for (int i = 0; i < 8; i++) {
                    float a = (kk == 0) ? a4[i].x : (kk == 1) ? a4[i].y
                            : (kk == 2) ? a4[i].z : a4[i].w;
                    acc[i] = fmaf(a, w, acc[i]);
                }
            }
        }
        __syncthreads();
    }
}

// ---------------------------------------------------------------------------
// Zero scratch buffers.
// ---------------------------------------------------------------------------
__global__ void zero_kernel(int total) {
    int i = blockIdx.x * blockDim.x + threadIdx.x;
    if (i < total) g_magg[i] = 0.f;
    if (i < 64) g_wsum[i] = 0.f;
}

// ---------------------------------------------------------------------------
// World MLP: per-node MLP on [z_h | z_h[0:3]-pos_world], summed over nodes.
// ---------------------------------------------------------------------------
__global__ void __launch_bounds__(THREADS)
world_kernel(const float* __restrict__ z_h, const float* __restrict__ pos_world,
             const float* __restrict__ Ww1, const float* __restrict__ bw1,
             const float* __restrict__ Ww2, const float* __restrict__ bw2,
             int N) {
    __shared__ float inp_s[TILE * 72];
    __shared__ float hid_s[TILE * HSTR];
    __shared__ float wbuf[2 * 8 * 128];
    __shared__ float red_s[4 * 64];

    const int t = threadIdx.x, warp = t >> 5, lane = t & 31;
    const int nb = blockIdx.x * TILE;

#pragma unroll
    for (int q = 0; q < 4; q++) {
        int e = warp * 4 + q;
        int n = nb + e;
        if (lane < 16) {
            int col = lane * 4;
            float4 v = make_float4(0.f, 0.f, 0.f, 0.f);
            if (n < N) v = *(const float4*)(z_h + (size_t)n * 64 + col);
            *(float4*)(inp_s + e * 72 + col) = v;
        } else if (lane < 18) {
            *(float4*)(inp_s + e * 72 + 64 + (lane - 16) * 4) =
                make_float4(0.f, 0.f, 0.f, 0.f);
        }
    }
    __syncthreads();
    if (t < TILE) {
        int n = nb + t;
        if (n < N) {
            float* r = inp_s + t * 72;
            r[64] = r[0] - pos_world[0];
            r[65] = r[1] - pos_world[1];
            r[66] = r[2] - pos_world[2];
        }
    }
    __syncthreads();

    gemm1_128(Ww1, bw1, 67, 72, inp_s, 72, hid_s, wbuf, t);
    float acc[8];
    gemm2_64(Ww2, hid_s, wbuf, t, acc);

    const int j = t & 63, eg = t >> 6, e0 = eg * 8;
    const float b2v = bw2[j];
    float s = 0.f;
#pragma unroll
    for (int i = 0; i < 8; i++)
        if (nb + e0 + i < N) s += acc[i] + b2v;
    red_s[eg * 64 + j] = s;
    __syncthreads();
    if (t < 64) {
        float tot = red_s[t] + red_s[64 + t] + red_s[128 + t] + red_s[192 + t];
        atomicAdd(&g_wsum[t], tot);
    }
}

// ---------------------------------------------------------------------------
// Edge kernel: gather, edge features, message MLP, gate MLP, scatter-add.
// ---------------------------------------------------------------------------
__global__ void __launch_bounds__(THREADS)
edge_kernel(const float* __restrict__ z_h, const int* __restrict__ ei,
            const float* __restrict__ We1, const float* __restrict__ be1,
            const float* __restrict__ We2, const float* __restrict__ be2,
            const float* __restrict__ Wg1, const float* __restrict__ bg1,
            const float* __restrict__ Wg2, const float* __restrict__ bg2,
            int E) {
    __shared__ float inp_s[TILE * 144];
    __shared__ float hid_s[TILE * HSTR];
    __shared__ float wbuf[2 * 8 * 128];
    __shared__ int src_s[TILE], tgt_s[TILE];
    __shared__ float gate_s[TILE];

    const int t = threadIdx.x, warp = t >> 5, lane = t & 31;
    const int ebase = blockIdx.x * TILE;

    if (t < TILE) {
        int e = ebase + t;
        src_s[t] = (e < E) ? ei[e] : 0;
        tgt_s[t] = (e < E) ? ei[E + e] : 0;
    }
    __syncthreads();

#pragma unroll
    for (int q = 0; q < 4; q++) {
        int e = warp * 4 + q;
        int row = (lane < 16) ? src_s[e] : tgt_s[e];
        int col = (lane & 15) * 4;
        float4 v = *(const float4*)(z_h + (size_t)row * 64 + col);
        int off = (lane < 16) ? col : 64 + col;
        *(float4*)(inp_s + e * 144 + off) = v;
    }
    __syncthreads();
    if (t < TILE) {
        float* r = inp_s + t * 144;
        float dx = r[0] - r[64], dy = r[1] - r[65], dz = r[2] - r[66];
        float dist = dx * dx + dy * dy + dz * dz;
        float a0 = r[3], a1 = r[4], a2 = r[5];
        float b0 = r[67], b1v = r[68], b2v = r[69];
        float cx = a1 * b2v - a2 * b1v;
        float cy = a2 * b0 - a0 * b2v;
        float cz = a0 * b1v - a1 * b0;
        float cn = sqrtf(cx * cx + cy * cy + cz * cz);
        r[128] = dx; r[129] = dy; r[130] = dz; r[131] = dist;
        r[132] = cx; r[133] = cy; r[134] = cz; r[135] = cn;
#pragma unroll
        for (int k = 136; k < 144; k++) r[k] = 0.f;
    }
    __syncthreads();

    // message MLP
    gemm1_128(We1, be1, 136, 144, inp_s, 144, hid_s, wbuf, t);
    float m_acc[8];
    gemm2_64(We2, hid_s, wbuf, t, m_acc);

    // gate MLP hidden (overwrites hid_s; safe — gemm2 fully synced)
    gemm1_128(Wg1, bg1, 136, 144, inp_s, 144, hid_s, wbuf, t);

    // gate dot: 8 lanes per edge, 16 k each, shuffle-reduce
    {
        int e = t >> 3, part = t & 7;
        const float* hrow = hid_s + e * HSTR + part * 16;
        float acc = 0.f;
#pragma unroll
        for (int kk = 0; kk < 16; kk++)
            acc = fmaf(hrow[kk], Wg2[part * 16 + kk], acc);
        acc += __shfl_xor_sync(0xffffffffu, acc, 4);
        acc += __shfl_xor_sync(0xffffffffu, acc, 2);
        acc += __shfl_xor_sync(0xffffffffu, acc, 1);
        if (part == 0) gate_s[e] = 1.f / (1.f + __expf(-(acc + bg2[0])));
    }
    __syncthreads();

    // scatter-add weighted messages
    const int j = t & 63, eg = t >> 6, e0 = eg * 8;
    const float b2 = be2[j];
#pragma unroll
    for (int i = 0; i < 8; i++) {
        int e = e0 + i;
        if (ebase + e < E) {
            float val = gate_s[e] * (m_acc[i] + b2);
            atomicAdd(g_magg + (size_t)tgt_s[e] * 64 + j, val);
        }
    }
}

// ---------------------------------------------------------------------------
// Node kernel: delta = MLP([z_h | m_agg + wsum])
// ---------------------------------------------------------------------------
__global__ void __launch_bounds__(THREADS)
node_kernel(const float* __restrict__ z_h,
            const float* __restrict__ Wn1, const float* __restrict__ bn1,
            const float* __restrict__ Wn2, const float* __restrict__ bn2,
            float* __restrict__ out, int N) {
    __shared__ float inp_s[TILE * 128];
    __shared__ float hid_s[TILE * HSTR];
    __shared__ float wbuf[2 * 8 * 128];

    const int t = threadIdx.x, warp = t >> 5, lane = t & 31;
    const int nb = blockIdx.x * TILE;

#pragma unroll
    for (int q = 0; q < 4; q++) {
        int e = warp * 4 + q;
        int n = nb + e;
        if (lane < 16) {
            int col = lane * 4;
            float4 v = make_float4(0.f, 0.f, 0.f, 0.f);
            if (n < N) v = *(const float4*)(z_h + (size_t)n * 64 + col);
            *(float4*)(inp_s + e * 128 + col) = v;
        } else {
            int col = (lane - 16) * 4;
            float4 v = make_float4(0.f, 0.f, 0.f, 0.f);
            if (n < N) {
                float4 mv = *(const float4*)(g_magg + (size_t)n * 64 + col);
                float4 ws = *(const float4*)(g_wsum + col);
                v = make_float4(mv.x + ws.x, mv.y + ws.y, mv.z + ws.z, mv.w + ws.w);
            }
            *(float4*)(inp_s + e * 128 + 64 + col) = v;
        }
    }
    __syncthreads();

    gemm1_128(Wn1, bn1, 128, 128, inp_s, 128, hid_s, wbuf, t);
    float acc[8];
    gemm2_64(Wn2, hid_s, wbuf, t, acc);

    const int j = t & 63, eg = t >> 6, e0 = eg * 8;
    const float b2v = bn2[j];
#pragma unroll
    for (int i = 0; i < 8; i++) {
        int n = nb + e0 + i;
        if (n < N) out[(size_t)n * 64 + j] = acc[i] + b2v;
    }
}

// ---------------------------------------------------------------------------
extern "C" void kernel_launch(void* const* d_in, const int* in_sizes, int n_in,
                              void* d_out, int out_size) {
    const float* z_h       = (const float*)d_in[0];
    const float* pos_world = (const float*)d_in[1];
    const int*   ei        = (const int*)d_in[2];
    const float* We1 = (const float*)d_in[3];
    const float* be1 = (const float*)d_in[4];
    const float* We2 = (const float*)d_in[5];
    const float* be2 = (const float*)d_in[6];
    const float* Wg1 = (const float*)d_in[7];
    const float* bg1 = (const float*)d_in[8];
    const float* Wg2 = (const float*)d_in[9];
    const float* bg2 = (const float*)d_in[10];
    const float* Wn1 = (const float*)d_in[11];
    const float* bn1 = (const float*)d_in[12];
    const float* Wn2 = (const float*)d_in[13];
    const float* bn2 = (const float*)d_in[14];
    const float* Ww1 = (const float*)d_in[15];
    const float* bw1 = (const float*)d_in[16];
    const float* Ww2 = (const float*)d_in[17];
    const float* bw2 = (const float*)d_in[18];

    const int N = in_sizes[0] / 64;
    const int E = in_sizes[2] / 2;
    float* out = (float*)d_out;

    const int total = N * 64;
    zero_kernel<<<(total + 255) / 256, 256>>>(total);
    world_kernel<<<(N + TILE - 1) / TILE, THREADS>>>(z_h, pos_world, Ww1, bw1, Ww2, bw2, N);
    edge_kernel<<<(E + TILE - 1) / TILE, THREADS>>>(z_h, ei, We1, be1, We2, be2,
                                                    Wg1, bg1, Wg2, bg2, E);
    node_kernel<<<(N + TILE - 1) / TILE, THREADS>>>(z_h, Wn1, bn1, Wn2, bn2, out, N);
}

// round 3
// speedup vs baseline: 3.4724x; 3.4724x over previous
#include <cuda_runtime.h>
#include <cuda_bf16.h>
#include <math.h>
#include <stdint.h>

// ===========================================================================
// Scratch (no allocations allowed)
// ===========================================================================
__device__ float g_magg[50048 * 64];
__device__ float g_wsum[64];

// ===========================================================================
// warp MMA: m16n8k16 row-col f32.bf16.bf16.f32  (sm_80+ PTX, no arch suffix)
// ===========================================================================
#define MMA_BF16(c, a0, a1, a2, a3, b0, b1) \
    asm volatile("mma.sync.aligned.m16n8k16.row.col.f32.bf16.bf16.f32 " \
        "{%0,%1,%2,%3},{%4,%5,%6,%7},{%8,%9},{%0,%1,%2,%3};" \
        : "+f"((c)[0]), "+f"((c)[1]), "+f"((c)[2]), "+f"((c)[3]) \
        : "r"(a0), "r"(a1), "r"(a2), "r"(a3), "r"(b0), "r"(b1))

__device__ __forceinline__ void pack_pair(float v0, float v1, uint32_t& hi, uint32_t& lo) {
    __nv_bfloat16 h0 = __float2bfloat16(v0);
    __nv_bfloat16 h1 = __float2bfloat16(v1);
    float r0 = v0 - __bfloat162float(h0);
    float r1 = v1 - __bfloat162float(h1);
    __nv_bfloat16 l0 = __float2bfloat16(r0);
    __nv_bfloat16 l1 = __float2bfloat16(r1);
    hi = ((uint32_t)__bfloat16_as_ushort(h1) << 16) | (uint32_t)__bfloat16_as_ushort(h0);
    lo = ((uint32_t)__bfloat16_as_ushort(l1) << 16) | (uint32_t)__bfloat16_as_ushort(l0);
}

// ===========================================================================
// Edge MMA kernel: persistent CTAs, 128 edges/tile, 8 warps x 16 edges.
// Weight smem layout: Wt[n][k] bf16, row stride 68 words (272B, mod32=4 ->
// conflict-free B-fragment LDS). Activation layout: [edge][k] bf16, row
// stride 76 words (mod32=12 -> conflict-free A-fragment LDS).
// ===========================================================================
#define ASTR 76
#define WSTR 68

// word offsets in dynamic smem
#define W1E_HI 0                 // 128*68 = 8704 words
#define W1E_LO 8704
#define W1G_HI 17408
#define W2_HI  26112             // 64*68 = 4352 words
#define W2_LO  30464
#define ACT_HI 34816             // 128*76 = 9728 words
#define ACT_LO 44544
#define TGT_S  54272             // 128 ints
#define GATE_S 54400             // 128 floats
#define BE1_S  54528             // 128
#define BG1_S  54656             // 128
#define WG2_S  54784             // 128
#define BE2_S  54912             // 64
#define EDGE_SMEM_WORDS 54976
#define EDGE_SMEM_BYTES (EDGE_SMEM_WORDS * 4)   // 219904

__global__ void __launch_bounds__(256, 1)
edge_mma_kernel(const float* __restrict__ z_h, const int* __restrict__ ei,
                const float* __restrict__ We1, const float* __restrict__ be1,
                const float* __restrict__ We2, const float* __restrict__ be2,
                const float* __restrict__ Wg1, const float* __restrict__ bg1,
                const float* __restrict__ Wg2, const float* __restrict__ bg2,
                int E) {
    extern __shared__ uint32_t smw[];
    float* smf = (float*)smw;
    int* smi = (int*)smw;
    uint16_t* smh = (uint16_t*)smw;

    const int t = threadIdx.x;
    const int w = t >> 5;           // warp 0..7
    const int l = t & 31;
    const int grp = l >> 2;         // groupID 0..7
    const int qid = l & 3;          // 0..3

    // ---------------- stage weights (once) ----------------
    for (int idx = t; idx < 136 * 128; idx += 256) {
        int k = idx >> 7, n = idx & 127;
        float v = We1[idx];
        __nv_bfloat16 h = __float2bfloat16(v);
        float r = v - __bfloat162float(h);
        smh[(W1E_HI + n * WSTR) * 2 + k] = __bfloat16_as_ushort(h);
        smh[(W1E_LO + n * WSTR) * 2 + k] = __bfloat16_as_ushort(__float2bfloat16(r));
        float vg = Wg1[idx];
        smh[(W1G_HI + n * WSTR) * 2 + k] = __bfloat16_as_ushort(__float2bfloat16(vg));
    }
    for (int idx = t; idx < 128 * 64; idx += 256) {
        int k = idx >> 6, n = idx & 63;
        float v = We2[idx];
        __nv_bfloat16 h = __float2bfloat16(v);
        float r = v - __bfloat162float(h);
        smh[(W2_HI + n * WSTR) * 2 + k] = __bfloat16_as_ushort(h);
        smh[(W2_LO + n * WSTR) * 2 + k] = __bfloat16_as_ushort(__float2bfloat16(r));
    }
    if (t < 128) {
        smf[BE1_S + t] = be1[t];
        smf[BG1_S + t] = bg1[t];
        smf[WG2_S + t] = Wg2[t];
    }
    if (t < 64) smf[BE2_S + t] = be2[t];
    const float bg2v = __ldg(&bg2[0]);
    __syncthreads();

    const int ntiles = (E + 127) / 128;
    // per-lane B-fragment base offset within an n-tile: n = nt*8 + grp
    const int bq = grp * WSTR + qid;

    for (int tile = blockIdx.x; tile < ntiles; tile += gridDim.x) {

        // ---------------- gather: 2 threads per edge ----------------
        {
            int e = t >> 1, half = t & 1;
            int eg = tile * 128 + e;
            int node = 0;
            if (eg < E) node = ei[half * E + eg];
            if (half) smi[TGT_S + e] = node;
            const float4* zp = (const float4*)(z_h + (size_t)node * 64);
            uint32_t* rh = smw + ACT_HI + e * ASTR + half * 32;
            uint32_t* rl = smw + ACT_LO + e * ASTR + half * 32;
#pragma unroll
            for (int q = 0; q < 16; q++) {
                float4 v = zp[q];
                uint32_t h0, l0, h1, l1;
                pack_pair(v.x, v.y, h0, l0);
                pack_pair(v.z, v.w, h1, l1);
                rh[2 * q] = h0; rh[2 * q + 1] = h1;
                rl[2 * q] = l0; rl[2 * q + 1] = l1;
            }
        }
        // ---------------- edge features (fp32 exact) ----------------
        if (t < 128) {
            int eg = tile * 128 + t;
            int s = 0, tt = 0;
            if (eg < E) { s = ei[eg]; tt = ei[E + eg]; }
            float4 q0 = *(const float4*)(z_h + (size_t)s * 64);
            float4 q1 = *(const float4*)(z_h + (size_t)s * 64 + 4);
            float4 r0 = *(const float4*)(z_h + (size_t)tt * 64);
            float4 r1 = *(const float4*)(z_h + (size_t)tt * 64 + 4);
            float dx = q0.x - r0.x, dy = q0.y - r0.y, dz = q0.z - r0.z;
            float dist = dx * dx + dy * dy + dz * dz;
            float cx = q1.x * r1.y - q1.y * r1.x;   // zs[4]*zt[5]-zs[5]*zt[4]
            float cy = q1.y * r0.w - q0.w * r1.y;   // zs[5]*zt[3]-zs[3]*zt[5]
            float cz = q0.w * r1.x - q1.x * r0.w;   // zs[3]*zt[4]-zs[4]*zt[3]
            float cn = sqrtf(cx * cx + cy * cy + cz * cz);
            uint32_t* rh = smw + ACT_HI + t * ASTR + 64;
            uint32_t* rl = smw + ACT_LO + t * ASTR + 64;
            uint32_t h0, l0;
            pack_pair(dx, dy, h0, l0);   rh[0] = h0; rl[0] = l0;
            pack_pair(dz, dist, h0, l0); rh[1] = h0; rl[1] = l0;
            pack_pair(cx, cy, h0, l0);   rh[2] = h0; rl[2] = l0;
            pack_pair(cz, cn, h0, l0);   rh[3] = h0; rl[3] = l0;
            rh[4] = 0; rh[5] = 0; rh[6] = 0; rh[7] = 0;
            rl[4] = 0; rl[5] = 0; rl[6] = 0; rl[7] = 0;
        }
        __syncthreads();

        // ---------------- build A1 fragments (K=144 -> 9 k-tiles) ----------------
        uint32_t a1h[36], a1l[36];
        {
            const int r0w = (w * 16 + grp) * ASTR + qid;
#pragma unroll
            for (int kt = 0; kt < 9; kt++) {
                int b0 = r0w + kt * 8;
                a1h[kt * 4 + 0] = smw[ACT_HI + b0];
                a1h[kt * 4 + 1] = smw[ACT_HI + b0 + 8 * ASTR];
                a1h[kt * 4 + 2] = smw[ACT_HI + b0 + 4];
                a1h[kt * 4 + 3] = smw[ACT_HI + b0 + 8 * ASTR + 4];
                a1l[kt * 4 + 0] = smw[ACT_LO + b0];
                a1l[kt * 4 + 1] = smw[ACT_LO + b0 + 8 * ASTR];
                a1l[kt * 4 + 2] = smw[ACT_LO + b0 + 4];
                a1l[kt * 4 + 3] = smw[ACT_LO + b0 + 8 * ASTR + 4];
            }
        }
        __syncthreads();   // protects act reads vs next-phase writes

        const int rowbase = (w * 16 + grp) * ASTR;   // hid write base (own rows)

        // ---------------- GEMM1 message: hid = relu(A @ We1 + be1) ----------------
#pragma unroll
        for (int nt2 = 0; nt2 < 8; nt2++) {
            const int ntA = nt2 * 2, ntB = ntA + 1;
            float cA[4] = {0.f, 0.f, 0.f, 0.f};
            float cB[4] = {0.f, 0.f, 0.f, 0.f};
            const int baseA = ntA * 8 * WSTR + bq;
            const int baseB = ntB * 8 * WSTR + bq;
#pragma unroll
            for (int kt = 0; kt < 9; kt++) {
                int oA = baseA + kt * 8, oB = baseB + kt * 8;
                uint32_t bhA0 = smw[W1E_HI + oA], bhA1 = smw[W1E_HI + oA + 4];
                uint32_t bhB0 = smw[W1E_HI + oB], bhB1 = smw[W1E_HI + oB + 4];
                uint32_t blA0 = smw[W1E_LO + oA], blA1 = smw[W1E_LO + oA + 4];
                uint32_t blB0 = smw[W1E_LO + oB], blB1 = smw[W1E_LO + oB + 4];
                MMA_BF16(cA, a1h[kt*4], a1h[kt*4+1], a1h[kt*4+2], a1h[kt*4+3], bhA0, bhA1);
                MMA_BF16(cB, a1h[kt*4], a1h[kt*4+1], a1h[kt*4+2], a1h[kt*4+3], bhB0, bhB1);
                MMA_BF16(cA, a1l[kt*4], a1l[kt*4+1], a1l[kt*4+2], a1l[kt*4+3], bhA0, bhA1);
                MMA_BF16(cB, a1l[kt*4], a1l[kt*4+1], a1l[kt*4+2], a1l[kt*4+3], bhB0, bhB1);
                MMA_BF16(cA, a1h[kt*4], a1h[kt*4+1], a1h[kt*4+2], a1h[kt*4+3], blA0, blA1);
                MMA_BF16(cB, a1h[kt*4], a1h[kt*4+1], a1h[kt*4+2], a1h[kt*4+3], blB0, blB1);
            }
            // epilogue: bias + relu + pack -> hid (aliases ACT words 0..63, own rows)
#pragma unroll
            for (int s = 0; s < 2; s++) {
                const float* c = s ? cB : cA;
                int nt = s ? ntB : ntA;
                int n0 = nt * 8 + 2 * qid;
                float v0 = fmaxf(c[0] + smf[BE1_S + n0], 0.f);
                float v1 = fmaxf(c[1] + smf[BE1_S + n0 + 1], 0.f);
                float v2 = fmaxf(c[2] + smf[BE1_S + n0], 0.f);
                float v3 = fmaxf(c[3] + smf[BE1_S + n0 + 1], 0.f);
                uint32_t h0, l0, h1, l1;
                pack_pair(v0, v1, h0, l0);
                pack_pair(v2, v3, h1, l1);
                int wi = rowbase + nt * 4 + qid;
                smw[ACT_HI + wi] = h0;
                smw[ACT_LO + wi] = l0;
                smw[ACT_HI + wi + 8 * ASTR] = h1;
                smw[ACT_LO + wi + 8 * ASTR] = l1;
            }
        }

        // ---------------- GEMM1 gate + fold dot(Wg2) ----------------
        float ps0 = 0.f, ps1 = 0.f;
#pragma unroll
        for (int nt = 0; nt < 16; nt++) {
            float c[4] = {0.f, 0.f, 0.f, 0.f};
            const int base = nt * 8 * WSTR + bq;
#pragma unroll
            for (int kt = 0; kt < 9; kt++) {
                int o = base + kt * 8;
                uint32_t b0 = smw[W1G_HI + o], b1 = smw[W1G_HI + o + 4];
                MMA_BF16(c, a1h[kt*4], a1h[kt*4+1], a1h[kt*4+2], a1h[kt*4+3], b0, b1);
                MMA_BF16(c, a1l[kt*4], a1l[kt*4+1], a1l[kt*4+2], a1l[kt*4+3], b0, b1);
            }
            int n0 = nt * 8 + 2 * qid;
            float w0 = smf[WG2_S + n0], w1 = smf[WG2_S + n0 + 1];
            float b0v = smf[BG1_S + n0], b1v = smf[BG1_S + n0 + 1];
            ps0 += fmaxf(c[0] + b0v, 0.f) * w0 + fmaxf(c[1] + b1v, 0.f) * w1;
            ps1 += fmaxf(c[2] + b0v, 0.f) * w0 + fmaxf(c[3] + b1v, 0.f) * w1;
        }
        ps0 += __shfl_xor_sync(0xffffffffu, ps0, 1);
        ps0 += __shfl_xor_sync(0xffffffffu, ps0, 2);
        ps1 += __shfl_xor_sync(0xffffffffu, ps1, 1);
        ps1 += __shfl_xor_sync(0xffffffffu, ps1, 2);
        if (qid == 0) {
            smf[GATE_S + w * 16 + grp] = 1.f / (1.f + __expf(-(ps0 + bg2v)));
            smf[GATE_S + w * 16 + grp + 8] = 1.f / (1.f + __expf(-(ps1 + bg2v)));
        }
        __syncwarp();

        // ---------------- GEMM2: m = hid @ We2 ; scatter gate*(m+be2) ----------------
        uint32_t a2h[32], a2l[32];
        {
            const int r0w = rowbase + qid;
#pragma unroll
            for (int kt = 0; kt < 8; kt++) {
                int b0 = r0w + kt * 8;
                a2h[kt * 4 + 0] = smw[ACT_HI + b0];
                a2h[kt * 4 + 1] = smw[ACT_HI + b0 + 8 * ASTR];
                a2h[kt * 4 + 2] = smw[ACT_HI + b0 + 4];
                a2h[kt * 4 + 3] = smw[ACT_HI + b0 + 8 * ASTR + 4];
                a2l[kt * 4 + 0] = smw[ACT_LO + b0];
                a2l[kt * 4 + 1] = smw[ACT_LO + b0 + 8 * ASTR];
                a2l[kt * 4 + 2] = smw[ACT_LO + b0 + 4];
                a2l[kt * 4 + 3] = smw[ACT_LO + b0 + 8 * ASTR + 4];
            }
        }
        const int row0 = w * 16 + grp;
        const float g0 = smf[GATE_S + row0];
        const float g1 = smf[GATE_S + row0 + 8];
        const int eg0 = tile * 128 + row0;
        const int tg0 = smi[TGT_S + row0];
        const int tg1 = smi[TGT_S + row0 + 8];

#pragma unroll
        for (int nt = 0; nt < 8; nt++) {
            float c[4] = {0.f, 0.f, 0.f, 0.f};
            const int base = nt * 8 * WSTR + bq;
#pragma unroll
            for (int kt = 0; kt < 8; kt++) {
                int o = base + kt * 8;
                uint32_t bh0 = smw[W2_HI + o], bh1 = smw[W2_HI + o + 4];
                uint32_t bl0 = smw[W2_LO + o], bl1 = smw[W2_LO + o + 4];
                MMA_BF16(c, a2h[kt*4], a2h[kt*4+1], a2h[kt*4+2], a2h[kt*4+3], bh0, bh1);
                MMA_BF16(c, a2l[kt*4], a2l[kt*4+1], a2l[kt*4+2], a2l[kt*4+3], bh0, bh1);
                MMA_BF16(c, a2h[kt*4], a2h[kt*4+1], a2h[kt*4+2], a2h[kt*4+3], bl0, bl1);
            }
            int n0 = nt * 8 + 2 * qid;
            float b0v = smf[BE2_S + n0], b1v = smf[BE2_S + n0 + 1];
            if (eg0 < E) {
                atomicAdd(g_magg + (size_t)tg0 * 64 + n0,     g0 * (c[0] + b0v));
                atomicAdd(g_magg + (size_t)tg0 * 64 + n0 + 1, g0 * (c[1] + b1v));
            }
            if (eg0 + 8 < E) {
                atomicAdd(g_magg + (size_t)tg1 * 64 + n0,     g1 * (c[2] + b0v));
                atomicAdd(g_magg + (size_t)tg1 * 64 + n0 + 1, g1 * (c[3] + b1v));
            }
        }
        __syncthreads();   // close tile: protect smem reuse across warps
    }
}

// ===========================================================================
// Scalar kernels (world / node / zero) — unchanged from passing R1 kernel
// ===========================================================================
#define THREADS 256
#define TILE 32
#define HSTR 132

__device__ __forceinline__ void load_chunk_w(const float* __restrict__ W, float* wb,
                                             int kbase, int KIN, int HT, int t) {
    const int total = 8 * HT;
    for (int idx = t; idx < total; idx += THREADS) {
        int kk = idx / HT;
        int h  = idx - kk * HT;
        int k  = kbase + kk;
        wb[idx] = (k < KIN) ? W[k * HT + h] : 0.0f;
    }
}

__device__ __forceinline__ void gemm1_128(const float* __restrict__ W1,
                                          const float* __restrict__ b1,
                                          int KIN, int KPAD,
                                          const float* inp_s, int istride,
                                          float* hid_s, float* wbuf, int t) {
    const int hg = t & 63, eg = t >> 6;
    const int j0 = hg * 2, e0 = eg * 8;
    float acc0[8], acc1[8];
#pragma unroll
    for (int i = 0; i < 8; i++) { acc0[i] = 0.f; acc1[i] = 0.f; }
    const int nc = KPAD >> 3;
    load_chunk_w(W1, wbuf, 0, KIN, 128, t);
    __syncthreads();
    for (int c = 0; c < nc; c++) {
        if (c + 1 < nc)
            load_chunk_w(W1, wbuf + ((c + 1) & 1) * 1024, (c + 1) * 8, KIN, 128, t);
        const float* wb = wbuf + (c & 1) * 1024;
        const int kbase = c * 8;
#pragma unroll
        for (int kq = 0; kq < 2; kq++) {
            float4 a4[8];
#pragma unroll
            for (int i = 0; i < 8; i++)
                a4[i] = *(const float4*)(inp_s + (e0 + i) * istride + kbase + kq * 4);
#pragma unroll
            for (int kk = 0; kk < 4; kk++) {
                float2 ww = *(const float2*)(wb + (kq * 4 + kk) * 128 + j0);
#pragma unroll
                for (int i = 0; i < 8; i++) {
                    float a = (kk == 0) ? a4[i].x : (kk == 1) ? a4[i].y
                            : (kk == 2) ? a4[i].z : a4[i].w;
                    acc0[i] = fmaf(a, ww.x, acc0[i]);
                    acc1[i] = fmaf(a, ww.y, acc1[i]);
                }
            }
        }
        __syncthreads();
    }
    const float bv0 = b1[j0], bv1 = b1[j0 + 1];
#pragma unroll
    for (int i = 0; i < 8; i++) {
        float2 v;
        v.x = fmaxf(acc0[i] + bv0, 0.f);
        v.y = fmaxf(acc1[i] + bv1, 0.f);
        *(float2*)(hid_s + (e0 + i) * HSTR + j0) = v;
    }
    __syncthreads();
}

__device__ __forceinline__ void gemm2_64(const float* __restrict__ W2,
                                         const float* hid_s, float* wbuf, int t,
                                         float acc[8]) {
    const int j = t & 63, eg = t >> 6, e0 = eg * 8;
#pragma unroll
    for (int i = 0; i < 8; i++) acc[i] = 0.f;
    load_chunk_w(W2, wbuf, 0, 128, 64, t);
    __syncthreads();
    for (int c = 0; c < 16; c++) {
        if (c + 1 < 16)
            load_chunk_w(W2, wbuf + ((c + 1) & 1) * 512, (c + 1) * 8, 128, 64, t);
        const float* wb = wbuf + (c & 1) * 512;
        const int kbase = c * 8;
#pragma unroll
        for (int kq = 0; kq < 2; kq++) {
            float4 a4[8];
#pragma unroll
            for (int i = 0; i < 8; i++)
                a4[i] = *(const float4*)(hid_s + (e0 + i) * HSTR + kbase + kq * 4);
#pragma unroll
            for (int kk = 0; kk < 4; kk++) {
                float ww = wb[(kq * 4 + kk) * 64 + j];
#pragma unroll
                for (int i = 0; i < 8; i++) {
                    float a = (kk == 0) ? a4[i].x : (kk == 1) ? a4[i].y
                            : (kk == 2) ? a4[i].z : a4[i].w;
                    acc[i] = fmaf(a, ww, acc[i]);
                }
            }
        }
        __syncthreads();
    }
}

__global__ void zero_kernel(int total) {
    int i = blockIdx.x * blockDim.x + threadIdx.x;
    if (i < total) g_magg[i] = 0.f;
    if (i < 64) g_wsum[i] = 0.f;
}

__global__ void __launch_bounds__(THREADS)
world_kernel(const float* __restrict__ z_h, const float* __restrict__ pos_world,
             const float* __restrict__ Ww1, const float* __restrict__ bw1,
             const float* __restrict__ Ww2, const float* __restrict__ bw2,
             int N) {
    __shared__ float inp_s[TILE * 72];
    __shared__ float hid_s[TILE * HSTR];
    __shared__ float wbuf[2 * 8 * 128];
    __shared__ float red_s[4 * 64];
    const int t = threadIdx.x, warp = t >> 5, lane = t & 31;
    const int nb = blockIdx.x * TILE;
#pragma unroll
    for (int q = 0; q < 4; q++) {
        int e = warp * 4 + q;
        int n = nb + e;
        if (lane < 16) {
            int col = lane * 4;
            float4 v = make_float4(0.f, 0.f, 0.f, 0.f);
            if (n < N) v = *(const float4*)(z_h + (size_t)n * 64 + col);
            *(float4*)(inp_s + e * 72 + col) = v;
        } else if (lane < 18) {
            *(float4*)(inp_s + e * 72 + 64 + (lane - 16) * 4) =
                make_float4(0.f, 0.f, 0.f, 0.f);
        }
    }
    __syncthreads();
    if (t < TILE) {
        int n = nb + t;
        if (n < N) {
            float* r = inp_s + t * 72;
            r[64] = r[0] - pos_world[0];
            r[65] = r[1] - pos_world[1];
            r[66] = r[2] - pos_world[2];
        }
    }
    __syncthreads();
    gemm1_128(Ww1, bw1, 67, 72, inp_s, 72, hid_s, wbuf, t);
    float acc[8];
    gemm2_64(Ww2, hid_s, wbuf, t, acc);
    const int j = t & 63, eg = t >> 6, e0 = eg * 8;
    const float b2v = bw2[j];
    float s = 0.f;
#pragma unroll
    for (int i = 0; i < 8; i++)
        if (nb + e0 + i < N) s += acc[i] + b2v;
    red_s[eg * 64 + j] = s;
    __syncthreads();
    if (t < 64) {
        float tot = red_s[t] + red_s[64 + t] + red_s[128 + t] + red_s[192 + t];
        atomicAdd(&g_wsum[t], tot);
    }
}

__global__ void __launch_bounds__(THREADS)
node_kernel(const float* __restrict__ z_h,
            const float* __restrict__ Wn1, const float* __restrict__ bn1,
            const float* __restrict__ Wn2, const float* __restrict__ bn2,
            float* __restrict__ out, int N) {
    __shared__ float inp_s[TILE * 128];
    __shared__ float hid_s[TILE * HSTR];
    __shared__ float wbuf[2 * 8 * 128];
    const int t = threadIdx.x, warp = t >> 5, lane = t & 31;
    const int nb = blockIdx.x * TILE;
#pragma unroll
    for (int q = 0; q < 4; q++) {
        int e = warp * 4 + q;
        int n = nb + e;
        if (lane < 16) {
            int col = lane * 4;
            float4 v = make_float4(0.f, 0.f, 0.f, 0.f);
            if (n < N) v = *(const float4*)(z_h + (size_t)n * 64 + col);
            *(float4*)(inp_s + e * 128 + col) = v;
        } else {
            int col = (lane - 16) * 4;
            float4 v = make_float4(0.f, 0.f, 0.f, 0.f);
            if (n < N) {
                float4 mv = *(const float4*)(g_magg + (size_t)n * 64 + col);
                float4 ws = *(const float4*)(g_wsum + col);
                v = make_float4(mv.x + ws.x, mv.y + ws.y, mv.z + ws.z, mv.w + ws.w);
            }
            *(float4*)(inp_s + e * 128 + 64 + col) = v;
        }
    }
    __syncthreads();
    gemm1_128(Wn1, bn1, 128, 128, inp_s, 128, hid_s, wbuf, t);
    float acc[8];
    gemm2_64(Wn2, hid_s, wbuf, t, acc);
    const int j = t & 63, eg = t >> 6, e0 = eg * 8;
    const float b2v = bn2[j];
#pragma unroll
    for (int i = 0; i < 8; i++) {
        int n = nb + e0 + i;
        if (n < N) out[(size_t)n * 64 + j] = acc[i] + b2v;
    }
}

// ===========================================================================
extern "C" void kernel_launch(void* const* d_in, const int* in_sizes, int n_in,
                              void* d_out, int out_size) {
    const float* z_h       = (const float*)d_in[0];
    const float* pos_world = (const float*)d_in[1];
    const int*   ei        = (const int*)d_in[2];
    const float* We1 = (const float*)d_in[3];
    const float* be1 = (const float*)d_in[4];
    const float* We2 = (const float*)d_in[5];
    const float* be2 = (const float*)d_in[6];
    const float* Wg1 = (const float*)d_in[7];
    const float* bg1 = (const float*)d_in[8];
    const float* Wg2 = (const float*)d_in[9];
    const float* bg2 = (const float*)d_in[10];
    const float* Wn1 = (const float*)d_in[11];
    const float* bn1 = (const float*)d_in[12];
    const float* Wn2 = (const float*)d_in[13];
    const float* bn2 = (const float*)d_in[14];
    const float* Ww1 = (const float*)d_in[15];
    const float* bw1 = (const float*)d_in[16];
    const float* Ww2 = (const float*)d_in[17];
    const float* bw2 = (const float*)d_in[18];

    const int N = in_sizes[0] / 64;
    const int E = in_sizes[2] / 2;
    float* out = (float*)d_out;

    static bool attr_set = false;
    if (!attr_set) {
        cudaFuncSetAttribute(edge_mma_kernel,
                             cudaFuncAttributeMaxDynamicSharedMemorySize, EDGE_SMEM_BYTES);
        attr_set = true;
    }

    const int total = N * 64;
    zero_kernel<<<(total + 255) / 256, 256>>>(total);
    world_kernel<<<(N + TILE - 1) / TILE, THREADS>>>(z_h, pos_world, Ww1, bw1, Ww2, bw2, N);
    edge_mma_kernel<<<148, 256, EDGE_SMEM_BYTES>>>(z_h, ei, We1, be1, We2, be2,
                                                   Wg1, bg1, Wg2, bg2, E);
    node_kernel<<<(N + TILE - 1) / TILE, THREADS>>>(z_h, Wn1, bn1, Wn2, bn2, out, N);
}

// round 5
// speedup vs baseline: 5.9498x; 1.7134x over previous
#include <cuda_runtime.h>
#include <cuda_bf16.h>
#include <math.h>
#include <stdint.h>

// ===========================================================================
// Scratch (no allocations allowed)
// ===========================================================================
__device__ float g_magg[50048 * 64];
__device__ float g_wsum[64];
__device__ uint32_t g_zpk[50048 * 32];   // prepacked bf16x2 z_h

// ===========================================================================
// warp MMA m16n8k16 bf16 (sm_80+ PTX, no arch suffix)
// ===========================================================================
#define MMA_BF16(c, a0, a1, a2, a3, b0, b1) \
    asm volatile("mma.sync.aligned.m16n8k16.row.col.f32.bf16.bf16.f32 " \
        "{%0,%1,%2,%3},{%4,%5,%6,%7},{%8,%9},{%0,%1,%2,%3};" \
        : "+f"((c)[0]), "+f"((c)[1]), "+f"((c)[2]), "+f"((c)[3]) \
        : "r"(a0), "r"(a1), "r"(a2), "r"(a3), "r"(b0), "r"(b1))

__device__ __forceinline__ uint32_t pack_hi(float v0, float v1) {
    return ((uint32_t)__bfloat16_as_ushort(__float2bfloat16(v1)) << 16) |
           (uint32_t)__bfloat16_as_ushort(__float2bfloat16(v0));
}

__device__ __forceinline__ void pack_pair(float v0, float v1, uint32_t& hi, uint32_t& lo) {
    __nv_bfloat16 h0 = __float2bfloat16(v0);
    __nv_bfloat16 h1 = __float2bfloat16(v1);
    float r0 = v0 - __bfloat162float(h0);
    float r1 = v1 - __bfloat162float(h1);
    hi = ((uint32_t)__bfloat16_as_ushort(h1) << 16) | (uint32_t)__bfloat16_as_ushort(h0);
    lo = ((uint32_t)__bfloat16_as_ushort(__float2bfloat16(r1)) << 16) |
         (uint32_t)__bfloat16_as_ushort(__float2bfloat16(r0));
}

#define ASTR 76   // activation row stride, words (mod32=12, conflict-free)
#define WSTR 68   // weight row stride, words (mod32=4, conflict-free)

// ===========================================================================
// prepack: z_h fp32 -> packed bf16x2
// ===========================================================================
__global__ void prepack_kernel(const float* __restrict__ z_h, int nwords) {
    int i = blockIdx.x * blockDim.x + threadIdx.x;
    if (i < nwords) {
        float2 v = ((const float2*)z_h)[i];
        g_zpk[i] = pack_hi(v.x, v.y);
    }
}

// ===========================================================================
// zero/init: g_magg = 0, g_wsum = N * bw2 (world bias folded in)
// ===========================================================================
__global__ void zero_kernel(int total, const float* __restrict__ bw2, float Nf) {
    int i = blockIdx.x * blockDim.x + threadIdx.x;
    if (i < total) g_magg[i] = 0.f;
    if (i < 64) g_wsum[i] = Nf * bw2[i];
}

// ===========================================================================
// EDGE kernel: acts 1-term bf16 (prepacked), weights 2-term hi/lo (gate hi)
// ===========================================================================
#define E_W1E_HI 0
#define E_W1E_LO 8704
#define E_W1G_HI 17408
#define E_W2_HI  26112
#define E_W2_LO  30464
#define E_ACT    34816
#define E_TGT    44544
#define E_GATE   44672
#define E_BE1    44800
#define E_BG1    44928
#define E_WG2    45056
#define E_BE2    45184
#define E_WORDS  45248
#define E_BYTES  (E_WORDS * 4)

__global__ void __launch_bounds__(256, 1)
edge_mma_kernel(const float* __restrict__ z_h, const int* __restrict__ ei,
                const float* __restrict__ We1, const float* __restrict__ be1,
                const float* __restrict__ We2, const float* __restrict__ be2,
                const float* __restrict__ Wg1, const float* __restrict__ bg1,
                const float* __restrict__ Wg2, const float* __restrict__ bg2,
                int E) {
    extern __shared__ uint32_t smw[];
    float* smf = (float*)smw;
    int* smi = (int*)smw;
    uint16_t* smh = (uint16_t*)smw;

    const int t = threadIdx.x;
    const int w = t >> 5;
    const int l = t & 31;
    const int grp = l >> 2;
    const int qid = l & 3;

    // stage weights once
    for (int idx = t; idx < 136 * 128; idx += 256) {
        int k = idx >> 7, n = idx & 127;
        float v = We1[idx];
        __nv_bfloat16 h = __float2bfloat16(v);
        float r = v - __bfloat162float(h);
        smh[(E_W1E_HI + n * WSTR) * 2 + k] = __bfloat16_as_ushort(h);
        smh[(E_W1E_LO + n * WSTR) * 2 + k] = __bfloat16_as_ushort(__float2bfloat16(r));
        smh[(E_W1G_HI + n * WSTR) * 2 + k] = __bfloat16_as_ushort(__float2bfloat16(Wg1[idx]));
    }
    for (int idx = t; idx < 128 * 64; idx += 256) {
        int k = idx >> 6, n = idx & 63;
        float v = We2[idx];
        __nv_bfloat16 h = __float2bfloat16(v);
        float r = v - __bfloat162float(h);
        smh[(E_W2_HI + n * WSTR) * 2 + k] = __bfloat16_as_ushort(h);
        smh[(E_W2_LO + n * WSTR) * 2 + k] = __bfloat16_as_ushort(__float2bfloat16(r));
    }
    if (t < 128) {
        smf[E_BE1 + t] = be1[t];
        smf[E_BG1 + t] = bg1[t];
        smf[E_WG2 + t] = Wg2[t];
    }
    if (t < 64) smf[E_BE2 + t] = be2[t];
    const float bg2v = __ldg(&bg2[0]);
    __syncthreads();

    const int ntiles = (E + 127) / 128;
    const int bq = grp * WSTR + qid;

    for (int tile = blockIdx.x; tile < ntiles; tile += gridDim.x) {
        // gather prepacked bf16 acts: 2 threads/edge, FULL 32-word row each
        {
            int e = t >> 1, half = t & 1;
            int eg = tile * 128 + e;
            int node = (eg < E) ? ei[half * E + eg] : 0;
            if (half) smi[E_TGT + e] = node;
            const uint4* zp = (const uint4*)(g_zpk + (size_t)node * 32);
            uint32_t* rh = smw + E_ACT + e * ASTR + half * 32;
#pragma unroll
            for (int q = 0; q < 8; q++) {
                uint4 v = zp[q];
                rh[4 * q] = v.x; rh[4 * q + 1] = v.y;
                rh[4 * q + 2] = v.z; rh[4 * q + 3] = v.w;
            }
        }
        // edge features (fp32 exact)
        if (t < 128) {
            int eg = tile * 128 + t;
            int s = 0, tt = 0;
            if (eg < E) { s = ei[eg]; tt = ei[E + eg]; }
            float4 q0 = *(const float4*)(z_h + (size_t)s * 64);
            float4 q1 = *(const float4*)(z_h + (size_t)s * 64 + 4);
            float4 r0 = *(const float4*)(z_h + (size_t)tt * 64);
            float4 r1 = *(const float4*)(z_h + (size_t)tt * 64 + 4);
            float dx = q0.x - r0.x, dy = q0.y - r0.y, dz = q0.z - r0.z;
            float dist = dx * dx + dy * dy + dz * dz;
            float cx = q1.x * r1.y - q1.y * r1.x;
            float cy = q1.y * r0.w - q0.w * r1.y;
            float cz = q0.w * r1.x - q1.x * r0.w;
            float cn = sqrtf(cx * cx + cy * cy + cz * cz);
            uint32_t* rh = smw + E_ACT + t * ASTR + 64;
            rh[0] = pack_hi(dx, dy);
            rh[1] = pack_hi(dz, dist);
            rh[2] = pack_hi(cx, cy);
            rh[3] = pack_hi(cz, cn);
            rh[4] = 0; rh[5] = 0; rh[6] = 0; rh[7] = 0;
        }
        __syncthreads();

        // A1 fragments (K=144 -> 9 kt), hi only
        uint32_t a1h[36];
        {
            const int r0w = (w * 16 + grp) * ASTR + qid;
#pragma unroll
            for (int kt = 0; kt < 9; kt++) {
                int b0 = r0w + kt * 8;
                a1h[kt * 4 + 0] = smw[E_ACT + b0];
                a1h[kt * 4 + 1] = smw[E_ACT + b0 + 8 * ASTR];
                a1h[kt * 4 + 2] = smw[E_ACT + b0 + 4];
                a1h[kt * 4 + 3] = smw[E_ACT + b0 + 8 * ASTR + 4];
            }
        }
        __syncthreads();

        const int rowbase = (w * 16 + grp) * ASTR;

        // GEMM1 message (weights 2-term), paired nt
#pragma unroll
        for (int nt2 = 0; nt2 < 8; nt2++) {
            const int ntA = nt2 * 2, ntB = ntA + 1;
            float cA[4] = {0.f, 0.f, 0.f, 0.f};
            float cB[4] = {0.f, 0.f, 0.f, 0.f};
            const int baseA = ntA * 8 * WSTR + bq;
            const int baseB = ntB * 8 * WSTR + bq;
#pragma unroll
            for (int kt = 0; kt < 9; kt++) {
                int oA = baseA + kt * 8, oB = baseB + kt * 8;
                uint32_t bhA0 = smw[E_W1E_HI + oA], bhA1 = smw[E_W1E_HI + oA + 4];
                uint32_t bhB0 = smw[E_W1E_HI + oB], bhB1 = smw[E_W1E_HI + oB + 4];
                uint32_t blA0 = smw[E_W1E_LO + oA], blA1 = smw[E_W1E_LO + oA + 4];
                uint32_t blB0 = smw[E_W1E_LO + oB], blB1 = smw[E_W1E_LO + oB + 4];
                MMA_BF16(cA, a1h[kt*4], a1h[kt*4+1], a1h[kt*4+2], a1h[kt*4+3], bhA0, bhA1);
                MMA_BF16(cB, a1h[kt*4], a1h[kt*4+1], a1h[kt*4+2], a1h[kt*4+3], bhB0, bhB1);
                MMA_BF16(cA, a1h[kt*4], a1h[kt*4+1], a1h[kt*4+2], a1h[kt*4+3], blA0, blA1);
                MMA_BF16(cB, a1h[kt*4], a1h[kt*4+1], a1h[kt*4+2], a1h[kt*4+3], blB0, blB1);
            }
#pragma unroll
            for (int s = 0; s < 2; s++) {
                const float* c = s ? cB : cA;
                int nt = s ? ntB : ntA;
                int n0 = nt * 8 + 2 * qid;
                float v0 = fmaxf(c[0] + smf[E_BE1 + n0], 0.f);
                float v1 = fmaxf(c[1] + smf[E_BE1 + n0 + 1], 0.f);
                float v2 = fmaxf(c[2] + smf[E_BE1 + n0], 0.f);
                float v3 = fmaxf(c[3] + smf[E_BE1 + n0 + 1], 0.f);
                int wi = rowbase + nt * 4 + qid;
                smw[E_ACT + wi] = pack_hi(v0, v1);
                smw[E_ACT + wi + 8 * ASTR] = pack_hi(v2, v3);
            }
        }

        // GEMM1 gate (1-term) + fold dot(Wg2)
        float ps0 = 0.f, ps1 = 0.f;
#pragma unroll
        for (int nt = 0; nt < 16; nt++) {
            float c[4] = {0.f, 0.f, 0.f, 0.f};
            const int base = nt * 8 * WSTR + bq;
#pragma unroll
            for (int kt = 0; kt < 9; kt++) {
                int o = base + kt * 8;
                uint32_t b0 = smw[E_W1G_HI + o], b1 = smw[E_W1G_HI + o + 4];
                MMA_BF16(c, a1h[kt*4], a1h[kt*4+1], a1h[kt*4+2], a1h[kt*4+3], b0, b1);
            }
            int n0 = nt * 8 + 2 * qid;
            float w0 = smf[E_WG2 + n0], w1 = smf[E_WG2 + n0 + 1];
            float b0v = smf[E_BG1 + n0], b1v = smf[E_BG1 + n0 + 1];
            ps0 += fmaxf(c[0] + b0v, 0.f) * w0 + fmaxf(c[1] + b1v, 0.f) * w1;
            ps1 += fmaxf(c[2] + b0v, 0.f) * w0 + fmaxf(c[3] + b1v, 0.f) * w1;
        }
        ps0 += __shfl_xor_sync(0xffffffffu, ps0, 1);
        ps0 += __shfl_xor_sync(0xffffffffu, ps0, 2);
        ps1 += __shfl_xor_sync(0xffffffffu, ps1, 1);
        ps1 += __shfl_xor_sync(0xffffffffu, ps1, 2);
        if (qid == 0) {
            smf[E_GATE + w * 16 + grp] = 1.f / (1.f + __expf(-(ps0 + bg2v)));
            smf[E_GATE + w * 16 + grp + 8] = 1.f / (1.f + __expf(-(ps1 + bg2v)));
        }
        __syncwarp();

        // GEMM2 (weights 2-term) + scatter
        uint32_t a2h[32];
        {
            const int r0w = rowbase + qid;
#pragma unroll
            for (int kt = 0; kt < 8; kt++) {
                int b0 = r0w + kt * 8;
                a2h[kt * 4 + 0] = smw[E_ACT + b0];
                a2h[kt * 4 + 1] = smw[E_ACT + b0 + 8 * ASTR];
                a2h[kt * 4 + 2] = smw[E_ACT + b0 + 4];
                a2h[kt * 4 + 3] = smw[E_ACT + b0 + 8 * ASTR + 4];
            }
        }
        const int row0 = w * 16 + grp;
        const float g0 = smf[E_GATE + row0];
        const float g1 = smf[E_GATE + row0 + 8];
        const int eg0 = tile * 128 + row0;
        const int tg0 = smi[E_TGT + row0];
        const int tg1 = smi[E_TGT + row0 + 8];

#pragma unroll
        for (int nt = 0; nt < 8; nt++) {
            float c[4] = {0.f, 0.f, 0.f, 0.f};
            const int base = nt * 8 * WSTR + bq;
#pragma unroll
            for (int kt = 0; kt < 8; kt++) {
                int o = base + kt * 8;
                uint32_t bh0 = smw[E_W2_HI + o], bh1 = smw[E_W2_HI + o + 4];
                uint32_t bl0 = smw[E_W2_LO + o], bl1 = smw[E_W2_LO + o + 4];
                MMA_BF16(c, a2h[kt*4], a2h[kt*4+1], a2h[kt*4+2], a2h[kt*4+3], bh0, bh1);
                MMA_BF16(c, a2h[kt*4], a2h[kt*4+1], a2h[kt*4+2], a2h[kt*4+3], bl0, bl1);
            }
            int n0 = nt * 8 + 2 * qid;
            float b0v = smf[E_BE2 + n0], b1v = smf[E_BE2 + n0 + 1];
            if (eg0 < E) {
                atomicAdd(g_magg + (size_t)tg0 * 64 + n0,     g0 * (c[0] + b0v));
                atomicAdd(g_magg + (size_t)tg0 * 64 + n0 + 1, g0 * (c[1] + b1v));
            }
            if (eg0 + 8 < E) {
                atomicAdd(g_magg + (size_t)tg1 * 64 + n0,     g1 * (c[2] + b0v));
                atomicAdd(g_magg + (size_t)tg1 * 64 + n0 + 1, g1 * (c[3] + b1v));
            }
        }
        __syncthreads();
    }
}

// ===========================================================================
// NODE kernel: MMA 3-term (precision-critical: m_agg dominated by world sum)
// ===========================================================================
#define N_W1_HI 0
#define N_W1_LO 8704
#define N_W2_HI 17408
#define N_W2_LO 21760
#define N_ACT_H 26112
#define N_ACT_L 35840
#define N_BN1   45568
#define N_WS    45696
#define N_WORDS 45760
#define N_BYTES (N_WORDS * 4)

__global__ void __launch_bounds__(256, 1)
node_mma_kernel(const float* __restrict__ z_h,
                const float* __restrict__ Wn1, const float* __restrict__ bn1,
                const float* __restrict__ Wn2, const float* __restrict__ bn2,
                float* __restrict__ out, int N) {
    extern __shared__ uint32_t smw[];
    float* smf = (float*)smw;
    uint16_t* smh = (uint16_t*)smw;

    const int t = threadIdx.x;
    const int w = t >> 5;
    const int l = t & 31;
    const int grp = l >> 2;
    const int qid = l & 3;

    for (int idx = t; idx < 128 * 128; idx += 256) {
        int k = idx >> 7, n = idx & 127;
        float v = Wn1[idx];
        __nv_bfloat16 h = __float2bfloat16(v);
        float r = v - __bfloat162float(h);
        smh[(N_W1_HI + n * WSTR) * 2 + k] = __bfloat16_as_ushort(h);
        smh[(N_W1_LO + n * WSTR) * 2 + k] = __bfloat16_as_ushort(__float2bfloat16(r));
    }
    for (int idx = t; idx < 128 * 64; idx += 256) {
        int k = idx >> 6, n = idx & 63;
        float v = Wn2[idx];
        __nv_bfloat16 h = __float2bfloat16(v);
        float r = v - __bfloat162float(h);
        smh[(N_W2_HI + n * WSTR) * 2 + k] = __bfloat16_as_ushort(h);
        smh[(N_W2_LO + n * WSTR) * 2 + k] = __bfloat16_as_ushort(__float2bfloat16(r));
    }
    if (t < 128) smf[N_BN1 + t] = bn1[t];
    if (t < 64) smf[N_WS + t] = g_wsum[t];
    __syncthreads();

    const int ntiles = (N + 127) / 128;
    const int bq = grp * WSTR + qid;

    for (int tile = blockIdx.x; tile < ntiles; tile += gridDim.x) {
        // gather: 2 threads/node; half0 = z_h, half1 = m_agg + wsum
        {
            int e = t >> 1, half = t & 1;
            int n = tile * 128 + e;
            bool v = (n < N);
            const float4* srcp = half
                ? (const float4*)(g_magg + (size_t)(v ? n : 0) * 64)
                : (const float4*)(z_h + (size_t)(v ? n : 0) * 64);
            const float4* wsp = (const float4*)(smf + N_WS);
            uint32_t* rh = smw + N_ACT_H + e * ASTR + half * 32;
            uint32_t* rl = smw + N_ACT_L + e * ASTR + half * 32;
#pragma unroll
            for (int q = 0; q < 16; q++) {
                float4 x = srcp[q];
                if (half) {
                    float4 ws = wsp[q];
                    x.x += ws.x; x.y += ws.y; x.z += ws.z; x.w += ws.w;
                }
                if (!v) x = make_float4(0.f, 0.f, 0.f, 0.f);
                uint32_t h0, l0, h1, l1;
                pack_pair(x.x, x.y, h0, l0);
                pack_pair(x.z, x.w, h1, l1);
                rh[2 * q] = h0; rh[2 * q + 1] = h1;
                rl[2 * q] = l0; rl[2 * q + 1] = l1;
            }
        }
        __syncthreads();

        uint32_t a1h[32], a1l[32];
        {
            const int r0w = (w * 16 + grp) * ASTR + qid;
#pragma unroll
            for (int kt = 0; kt < 8; kt++) {
                int b0 = r0w + kt * 8;
                a1h[kt * 4 + 0] = smw[N_ACT_H + b0];
                a1h[kt * 4 + 1] = smw[N_ACT_H + b0 + 8 * ASTR];
                a1h[kt * 4 + 2] = smw[N_ACT_H + b0 + 4];
                a1h[kt * 4 + 3] = smw[N_ACT_H + b0 + 8 * ASTR + 4];
                a1l[kt * 4 + 0] = smw[N_ACT_L + b0];
                a1l[kt * 4 + 1] = smw[N_ACT_L + b0 + 8 * ASTR];
                a1l[kt * 4 + 2] = smw[N_ACT_L + b0 + 4];
                a1l[kt * 4 + 3] = smw[N_ACT_L + b0 + 8 * ASTR + 4];
            }
        }
        __syncthreads();

        const int rowbase = (w * 16 + grp) * ASTR;

        // GEMM1 3-term
#pragma unroll
        for (int nt = 0; nt < 16; nt++) {
            float c[4] = {0.f, 0.f, 0.f, 0.f};
            const int base = nt * 8 * WSTR + bq;
#pragma unroll
            for (int kt = 0; kt < 8; kt++) {
                int o = base + kt * 8;
                uint32_t bh0 = smw[N_W1_HI + o], bh1 = smw[N_W1_HI + o + 4];
                uint32_t bl0 = smw[N_W1_LO + o], bl1 = smw[N_W1_LO + o + 4];
                MMA_BF16(c, a1h[kt*4], a1h[kt*4+1], a1h[kt*4+2], a1h[kt*4+3], bh0, bh1);
                MMA_BF16(c, a1l[kt*4], a1l[kt*4+1], a1l[kt*4+2], a1l[kt*4+3], bh0, bh1);
                MMA_BF16(c, a1h[kt*4], a1h[kt*4+1], a1h[kt*4+2], a1h[kt*4+3], bl0, bl1);
            }
            int n0 = nt * 8 + 2 * qid;
            float v0 = fmaxf(c[0] + smf[N_BN1 + n0], 0.f);
            float v1 = fmaxf(c[1] + smf[N_BN1 + n0 + 1], 0.f);
            float v2 = fmaxf(c[2] + smf[N_BN1 + n0], 0.f);
            float v3 = fmaxf(c[3] + smf[N_BN1 + n0 + 1], 0.f);
            uint32_t h0, l0, h1, l1;
            pack_pair(v0, v1, h0, l0);
            pack_pair(v2, v3, h1, l1);
            int wi = rowbase + nt * 4 + qid;
            smw[N_ACT_H + wi] = h0;
            smw[N_ACT_L + wi] = l0;
            smw[N_ACT_H + wi + 8 * ASTR] = h1;
            smw[N_ACT_L + wi + 8 * ASTR] = l1;
        }

        // GEMM2 3-term, direct store
        uint32_t a2h[32], a2l[32];
        {
            const int r0w = rowbase + qid;
#pragma unroll
            for (int kt = 0; kt < 8; kt++) {
                int b0 = r0w + kt * 8;
                a2h[kt * 4 + 0] = smw[N_ACT_H + b0];
                a2h[kt * 4 + 1] = smw[N_ACT_H + b0 + 8 * ASTR];
                a2h[kt * 4 + 2] = smw[N_ACT_H + b0 + 4];
                a2h[kt * 4 + 3] = smw[N_ACT_H + b0 + 8 * ASTR + 4];
                a2l[kt * 4 + 0] = smw[N_ACT_L + b0];
                a2l[kt * 4 + 1] = smw[N_ACT_L + b0 + 8 * ASTR];
                a2l[kt * 4 + 2] = smw[N_ACT_L + b0 + 4];
                a2l[kt * 4 + 3] = smw[N_ACT_L + b0 + 8 * ASTR + 4];
            }
        }
        const int r0 = tile * 128 + w * 16 + grp;
        const int r1 = r0 + 8;

#pragma unroll
        for (int nt = 0; nt < 8; nt++) {
            float c[4] = {0.f, 0.f, 0.f, 0.f};
            const int base = nt * 8 * WSTR + bq;
#pragma unroll
            for (int kt = 0; kt < 8; kt++) {
                int o = base + kt * 8;
                uint32_t bh0 = smw[N_W2_HI + o], bh1 = smw[N_W2_HI + o + 4];
                uint32_t bl0 = smw[N_W2_LO + o], bl1 = smw[N_W2_LO + o + 4];
                MMA_BF16(c, a2h[kt*4], a2h[kt*4+1], a2h[kt*4+2], a2h[kt*4+3], bh0, bh1);
                MMA_BF16(c, a2l[kt*4], a2l[kt*4+1], a2l[kt*4+2], a2l[kt*4+3], bh0, bh1);
                MMA_BF16(c, a2h[kt*4], a2h[kt*4+1], a2h[kt*4+2], a2h[kt*4+3], bl0, bl1);
            }
            int n0 = nt * 8 + 2 * qid;
            float b0v = __ldg(&bn2[n0]), b1v = __ldg(&bn2[n0 + 1]);
            if (r0 < N) {
                float2 o2 = make_float2(c[0] + b0v, c[1] + b1v);
                *(float2*)(out + (size_t)r0 * 64 + n0) = o2;
            }
            if (r1 < N) {
                float2 o2 = make_float2(c[2] + b0v, c[3] + b1v);
                *(float2*)(out + (size_t)r1 * 64 + n0) = o2;
            }
        }
        __syncthreads();
    }
}

// ===========================================================================
// WORLD kernel: MMA 3-term, per-block accumulate, one reduce at the end
// ===========================================================================
#define W_W1_HI 0
#define W_W1_LO 8704
#define W_W2_HI 17408
#define W_W2_LO 21760
#define W_ACT_H 26112
#define W_ACT_L 35840
#define W_BW1   45568
#define W_RED   45696
#define W_WORDS 46208
#define W_BYTES (W_WORDS * 4)

__global__ void __launch_bounds__(256, 1)
world_mma_kernel(const float* __restrict__ z_h, const float* __restrict__ pos_world,
                 const float* __restrict__ Ww1, const float* __restrict__ bw1,
                 const float* __restrict__ Ww2, int N) {
    extern __shared__ uint32_t smw[];
    float* smf = (float*)smw;
    uint16_t* smh = (uint16_t*)smw;

    const int t = threadIdx.x;
    const int w = t >> 5;
    const int l = t & 31;
    const int grp = l >> 2;
    const int qid = l & 3;

    // zero W1 region (k padding 67..79 must be 0)
    for (int i = t; i < 17408; i += 256) smw[W_W1_HI + i] = 0;
    __syncthreads();
    for (int idx = t; idx < 67 * 128; idx += 256) {
        int k = idx >> 7, n = idx & 127;
        float v = Ww1[idx];
        __nv_bfloat16 h = __float2bfloat16(v);
        float r = v - __bfloat162float(h);
        smh[(W_W1_HI + n * WSTR) * 2 + k] = __bfloat16_as_ushort(h);
        smh[(W_W1_LO + n * WSTR) * 2 + k] = __bfloat16_as_ushort(__float2bfloat16(r));
    }
    for (int idx = t; idx < 128 * 64; idx += 256) {
        int k = idx >> 6, n = idx & 63;
        float v = Ww2[idx];
        __nv_bfloat16 h = __float2bfloat16(v);
        float r = v - __bfloat162float(h);
        smh[(W_W2_HI + n * WSTR) * 2 + k] = __bfloat16_as_ushort(h);
        smh[(W_W2_LO + n * WSTR) * 2 + k] = __bfloat16_as_ushort(__float2bfloat16(r));
    }
    if (t < 128) smf[W_BW1 + t] = bw1[t];
    const float p0 = __ldg(&pos_world[0]);
    const float p1 = __ldg(&pos_world[1]);
    const float p2 = __ldg(&pos_world[2]);
    __syncthreads();

    const int ntiles = (N + 127) / 128;
    const int bq = grp * WSTR + qid;

    float accs[16];
#pragma unroll
    for (int i = 0; i < 16; i++) accs[i] = 0.f;

    for (int tile = blockIdx.x; tile < ntiles; tile += gridDim.x) {
        // gather: 2 threads/node, z cols 0..31 / 32..63
        {
            int e = t >> 1, half = t & 1;
            int n = tile * 128 + e;
            bool v = (n < N);
            const float4* zp = (const float4*)(z_h + (size_t)(v ? n : 0) * 64) + half * 8;
            uint32_t* rh = smw + W_ACT_H + e * ASTR + half * 16;
            uint32_t* rl = smw + W_ACT_L + e * ASTR + half * 16;
#pragma unroll
            for (int q = 0; q < 8; q++) {
                float4 x = zp[q];
                if (!v) x = make_float4(0.f, 0.f, 0.f, 0.f);
                uint32_t h0, l0, h1, l1;
                pack_pair(x.x, x.y, h0, l0);
                pack_pair(x.z, x.w, h1, l1);
                rh[2 * q] = h0; rh[2 * q + 1] = h1;
                rl[2 * q] = l0; rl[2 * q + 1] = l1;
            }
        }
        if (t < 128) {
            int n = tile * 128 + t;
            bool v = (n < N);
            float4 z0 = *(const float4*)(z_h + (size_t)(v ? n : 0) * 64);
            float d0 = v ? z0.x - p0 : 0.f;
            float d1 = v ? z0.y - p1 : 0.f;
            float d2 = v ? z0.z - p2 : 0.f;
            uint32_t* rh = smw + W_ACT_H + t * ASTR + 32;
            uint32_t* rl = smw + W_ACT_L + t * ASTR + 32;
            uint32_t h0, l0, h1, l1;
            pack_pair(d0, d1, h0, l0);
            pack_pair(d2, 0.f, h1, l1);
            rh[0] = h0; rl[0] = l0;
            rh[1] = h1; rl[1] = l1;
#pragma unroll
            for (int q = 2; q < 8; q++) { rh[q] = 0; rl[q] = 0; }
        }
        __syncthreads();

        uint32_t a1h[20], a1l[20];
        {
            const int r0w = (w * 16 + grp) * ASTR + qid;
#pragma unroll
            for (int kt = 0; kt < 5; kt++) {
                int b0 = r0w + kt * 8;
                a1h[kt * 4 + 0] = smw[W_ACT_H + b0];
                a1h[kt * 4 + 1] = smw[W_ACT_H + b0 + 8 * ASTR];
                a1h[kt * 4 + 2] = smw[W_ACT_H + b0 + 4];
                a1h[kt * 4 + 3] = smw[W_ACT_H + b0 + 8 * ASTR + 4];
                a1l[kt * 4 + 0] = smw[W_ACT_L + b0];
                a1l[kt * 4 + 1] = smw[W_ACT_L + b0 + 8 * ASTR];
                a1l[kt * 4 + 2] = smw[W_ACT_L + b0 + 4];
                a1l[kt * 4 + 3] = smw[W_ACT_L + b0 + 8 * ASTR + 4];
            }
        }
        __syncthreads();

        const int rowbase = (w * 16 + grp) * ASTR;

        // GEMM1 3-term (5 kt)
#pragma unroll
        for (int nt = 0; nt < 16; nt++) {
            float c[4] = {0.f, 0.f, 0.f, 0.f};
            const int base = nt * 8 * WSTR + bq;
#pragma unroll
            for (int kt = 0; kt < 5; kt++) {
                int o = base + kt * 8;
                uint32_t bh0 = smw[W_W1_HI + o], bh1 = smw[W_W1_HI + o + 4];
                uint32_t bl0 = smw[W_W1_LO + o], bl1 = smw[W_W1_LO + o + 4];
                MMA_BF16(c, a1h[kt*4], a1h[kt*4+1], a1h[kt*4+2], a1h[kt*4+3], bh0, bh1);
                MMA_BF16(c, a1l[kt*4], a1l[kt*4+1], a1l[kt*4+2], a1l[kt*4+3], bh0, bh1);
                MMA_BF16(c, a1h[kt*4], a1h[kt*4+1], a1h[kt*4+2], a1h[kt*4+3], bl0, bl1);
            }
            int n0 = nt * 8 + 2 * qid;
            float v0 = fmaxf(c[0] + smf[W_BW1 + n0], 0.f);
            float v1 = fmaxf(c[1] + smf[W_BW1 + n0 + 1], 0.f);
            float v2 = fmaxf(c[2] + smf[W_BW1 + n0], 0.f);
            float v3 = fmaxf(c[3] + smf[W_BW1 + n0 + 1], 0.f);
            uint32_t h0, l0, h1, l1;
            pack_pair(v0, v1, h0, l0);
            pack_pair(v2, v3, h1, l1);
            int wi = rowbase + nt * 4 + qid;
            smw[W_ACT_H + wi] = h0;
            smw[W_ACT_L + wi] = l0;
            smw[W_ACT_H + wi + 8 * ASTR] = h1;
            smw[W_ACT_L + wi + 8 * ASTR] = l1;
        }

        // GEMM2 3-term, masked accumulate into accs
        uint32_t a2h[32], a2l[32];
        {
            const int r0w = rowbase + qid;
#pragma unroll
            for (int kt = 0; kt < 8; kt++) {
                int b0 = r0w + kt * 8;
                a2h[kt * 4 + 0] = smw[W_ACT_H + b0];
                a2h[kt * 4 + 1] = smw[W_ACT_H + b0 + 8 * ASTR];
                a2h[kt * 4 + 2] = smw[W_ACT_H + b0 + 4];
                a2h[kt * 4 + 3] = smw[W_ACT_H + b0 + 8 * ASTR + 4];
                a2l[kt * 4 + 0] = smw[W_ACT_L + b0];
                a2l[kt * 4 + 1] = smw[W_ACT_L + b0 + 8 * ASTR];
                a2l[kt * 4 + 2] = smw[W_ACT_L + b0 + 4];
                a2l[kt * 4 + 3] = smw[W_ACT_L + b0 + 8 * ASTR + 4];
            }
        }
        const int r0 = tile * 128 + w * 16 + grp;
        const float m0 = (r0 < N) ? 1.f : 0.f;
        const float m1 = (r0 + 8 < N) ? 1.f : 0.f;

#pragma unroll
        for (int nt = 0; nt < 8; nt++) {
            float c[4] = {0.f, 0.f, 0.f, 0.f};
            const int base = nt * 8 * WSTR + bq;
#pragma unroll
            for (int kt = 0; kt < 8; kt++) {
                int o = base + kt * 8;
                uint32_t bh0 = smw[W_W2_HI + o], bh1 = smw[W_W2_HI + o + 4];
                uint32_t bl0 = smw[W_W2_LO + o], bl1 = smw[W_W2_LO + o + 4];
                MMA_BF16(c, a2h[kt*4], a2h[kt*4+1], a2h[kt*4+2], a2h[kt*4+3], bh0, bh1);
                MMA_BF16(c, a2l[kt*4], a2l[kt*4+1], a2l[kt*4+2], a2l[kt*4+3], bh0, bh1);
                MMA_BF16(c, a2h[kt*4], a2h[kt*4+1], a2h[kt*4+2], a2h[kt*4+3], bl0, bl1);
            }
            accs[nt * 2]     += m0 * c[0] + m1 * c[2];
            accs[nt * 2 + 1] += m0 * c[1] + m1 * c[3];
        }
        __syncthreads();
    }

    // reduce across grp, then across warps, then atomics
#pragma unroll
    for (int i = 0; i < 16; i++) {
        accs[i] += __shfl_xor_sync(0xffffffffu, accs[i], 4);
        accs[i] += __shfl_xor_sync(0xffffffffu, accs[i], 8);
        accs[i] += __shfl_xor_sync(0xffffffffu, accs[i], 16);
    }
    if (l < 4) {
#pragma unroll
        for (int nt = 0; nt < 8; nt++) {
            smf[W_RED + w * 64 + nt * 8 + 2 * l]     = accs[nt * 2];
            smf[W_RED + w * 64 + nt * 8 + 2 * l + 1] = accs[nt * 2 + 1];
        }
    }
    __syncthreads();
    if (t < 64) {
        float s = 0.f;
#pragma unroll
        for (int ww = 0; ww < 8; ww++) s += smf[W_RED + ww * 64 + t];
        atomicAdd(&g_wsum[t], s);
    }
}

// ===========================================================================
extern "C" void kernel_launch(void* const* d_in, const int* in_sizes, int n_in,
                              void* d_out, int out_size) {
    const float* z_h       = (const float*)d_in[0];
    const float* pos_world = (const float*)d_in[1];
    const int*   ei        = (const int*)d_in[2];
    const float* We1 = (const float*)d_in[3];
    const float* be1 = (const float*)d_in[4];
    const float* We2 = (const float*)d_in[5];
    const float* be2 = (const float*)d_in[6];
    const float* Wg1 = (const float*)d_in[7];
    const float* bg1 = (const float*)d_in[8];
    const float* Wg2 = (const float*)d_in[9];
    const float* bg2 = (const float*)d_in[10];
    const float* Wn1 = (const float*)d_in[11];
    const float* bn1 = (const float*)d_in[12];
    const float* Wn2 = (const float*)d_in[13];
    const float* bn2 = (const float*)d_in[14];
    const float* Ww1 = (const float*)d_in[15];
    const float* bw1 = (const float*)d_in[16];
    const float* Ww2 = (const float*)d_in[17];
    const float* bw2 = (const float*)d_in[18];

    const int N = in_sizes[0] / 64;
    const int E = in_sizes[2] / 2;
    float* out = (float*)d_out;

    cudaFuncSetAttribute(edge_mma_kernel,
                         cudaFuncAttributeMaxDynamicSharedMemorySize, E_BYTES);
    cudaFuncSetAttribute(node_mma_kernel,
                         cudaFuncAttributeMaxDynamicSharedMemorySize, N_BYTES);
    cudaFuncSetAttribute(world_mma_kernel,
                         cudaFuncAttributeMaxDynamicSharedMemorySize, W_BYTES);

    const int total = N * 64;
    zero_kernel<<<(total + 255) / 256, 256>>>(total, bw2, (float)N);
    prepack_kernel<<<(N * 32 + 255) / 256, 256>>>(z_h, N * 32);
    world_mma_kernel<<<148, 256, W_BYTES>>>(z_h, pos_world, Ww1, bw1, Ww2, N);
    edge_mma_kernel<<<148, 256, E_BYTES>>>(z_h, ei, We1, be1, We2, be2,
                                           Wg1, bg1, Wg2, bg2, E);
    node_mma_kernel<<<148, 256, N_BYTES>>>(z_h, Wn1, bn1, Wn2, bn2, out, N);
}

// round 6
// speedup vs baseline: 7.5158x; 1.2632x over previous
#include <cuda_runtime.h>
#include <cuda_bf16.h>
#include <math.h>
#include <stdint.h>

// ===========================================================================
// Scratch (no allocations allowed)
// ===========================================================================
__device__ float g_magg[50048 * 64];
__device__ float g_wsum[64];
__device__ uint32_t g_zpk[50048 * 32];   // prepacked bf16x2 z_h

// ===========================================================================
// warp MMA m16n8k16 bf16 (sm_80+ PTX, no arch suffix)
// ===========================================================================
#define MMA_BF16(c, a0, a1, a2, a3, b0, b1) \
    asm volatile("mma.sync.aligned.m16n8k16.row.col.f32.bf16.bf16.f32 " \
        "{%0,%1,%2,%3},{%4,%5,%6,%7},{%8,%9},{%0,%1,%2,%3};" \
        : "+f"((c)[0]), "+f"((c)[1]), "+f"((c)[2]), "+f"((c)[3]) \
        : "r"(a0), "r"(a1), "r"(a2), "r"(a3), "r"(b0), "r"(b1))

__device__ __forceinline__ uint32_t pack_hi(float v0, float v1) {
    return ((uint32_t)__bfloat16_as_ushort(__float2bfloat16(v1)) << 16) |
           (uint32_t)__bfloat16_as_ushort(__float2bfloat16(v0));
}

__device__ __forceinline__ void pack_pair(float v0, float v1, uint32_t& hi, uint32_t& lo) {
    __nv_bfloat16 h0 = __float2bfloat16(v0);
    __nv_bfloat16 h1 = __float2bfloat16(v1);
    float r0 = v0 - __bfloat162float(h0);
    float r1 = v1 - __bfloat162float(h1);
    hi = ((uint32_t)__bfloat16_as_ushort(h1) << 16) | (uint32_t)__bfloat16_as_ushort(h0);
    lo = ((uint32_t)__bfloat16_as_ushort(__float2bfloat16(r1)) << 16) |
         (uint32_t)__bfloat16_as_ushort(__float2bfloat16(r0));
}

#define ASTR 76   // activation row stride, words (mod32=12, conflict-free)
#define WSTR 68   // weight row stride, words (mod32=4, conflict-free)

// ===========================================================================
// prepack: z_h fp32 -> packed bf16x2
// ===========================================================================
__global__ void prepack_kernel(const float* __restrict__ z_h, int nwords) {
    int i = blockIdx.x * blockDim.x + threadIdx.x;
    if (i < nwords) {
        float2 v = ((const float2*)z_h)[i];
        g_zpk[i] = pack_hi(v.x, v.y);
    }
}

// ===========================================================================
// zero/init: g_magg = 0, g_wsum = N * bw2 (world bias folded in)
// ===========================================================================
__global__ void zero_kernel(int total, const float* __restrict__ bw2, float Nf) {
    int i = blockIdx.x * blockDim.x + threadIdx.x;
    if (i < total) g_magg[i] = 0.f;
    if (i < 64) g_wsum[i] = Nf * bw2[i];
}

// ===========================================================================
// EDGE kernel: 384 threads, 12 warps x 32 edges, all weights 1-term bf16.
// ===========================================================================
#define ETHREADS 384
#define ETILE    384

#define E_W1E   0                    // 128*68 = 8704 words
#define E_W1G   8704
#define E_W2    17408                // 64*68 = 4352 words
#define E_ACT   21760                // 384*76 = 29184 words
#define E_TGT   50944                // 384
#define E_GATE  51328                // 384
#define E_BE1   51712
#define E_BG1   51840
#define E_WG2   51968
#define E_BE2   52096
#define E_WORDS 52160
#define E_BYTES (E_WORDS * 4)        // 208640

__global__ void __launch_bounds__(ETHREADS, 1)
edge_mma_kernel(const float* __restrict__ z_h, const int* __restrict__ ei,
                const float* __restrict__ We1, const float* __restrict__ be1,
                const float* __restrict__ We2, const float* __restrict__ be2,
                const float* __restrict__ Wg1, const float* __restrict__ bg1,
                const float* __restrict__ Wg2, const float* __restrict__ bg2,
                int E) {
    extern __shared__ uint32_t smw[];
    float* smf = (float*)smw;
    int* smi = (int*)smw;
    uint16_t* smh = (uint16_t*)smw;

    const int t = threadIdx.x;
    const int w = t >> 5;           // warp 0..11
    const int l = t & 31;
    const int grp = l >> 2;         // 0..7
    const int qid = l & 3;          // 0..3

    // ---- stage weights once (1-term bf16) ----
    for (int idx = t; idx < 136 * 128; idx += ETHREADS) {
        int k = idx >> 7, n = idx & 127;
        smh[(E_W1E + n * WSTR) * 2 + k] = __bfloat16_as_ushort(__float2bfloat16(We1[idx]));
        smh[(E_W1G + n * WSTR) * 2 + k] = __bfloat16_as_ushort(__float2bfloat16(Wg1[idx]));
    }
    for (int idx = t; idx < 128 * 64; idx += ETHREADS) {
        int k = idx >> 6, n = idx & 63;
        smh[(E_W2 + n * WSTR) * 2 + k] = __bfloat16_as_ushort(__float2bfloat16(We2[idx]));
    }
    if (t < 128) {
        smf[E_BE1 + t] = be1[t];
        smf[E_BG1 + t] = bg1[t];
        smf[E_WG2 + t] = Wg2[t];
    }
    if (t < 64) smf[E_BE2 + t] = be2[t];
    const float bg2v = __ldg(&bg2[0]);
    __syncthreads();

    const int ntiles = (E + ETILE - 1) / ETILE;
    const int bq = grp * WSTR + qid;

    for (int tile = blockIdx.x; tile < ntiles; tile += gridDim.x) {
        // ---- gather: 1 thread per edge, full src+tgt packed rows ----
        {
            const int e = t;
            const int eg = tile * ETILE + e;
            const int sN = (eg < E) ? ei[eg] : 0;
            const int tN = (eg < E) ? ei[E + eg] : 0;
            smi[E_TGT + e] = tN;
            uint32_t* r = smw + E_ACT + e * ASTR;
            const uint4* zs = (const uint4*)(g_zpk + (size_t)sN * 32);
            const uint4* zt = (const uint4*)(g_zpk + (size_t)tN * 32);
#pragma unroll
            for (int q = 0; q < 8; q++) {
                uint4 v = zs[q];
                r[4 * q] = v.x; r[4 * q + 1] = v.y; r[4 * q + 2] = v.z; r[4 * q + 3] = v.w;
            }
#pragma unroll
            for (int q = 0; q < 8; q++) {
                uint4 v = zt[q];
                r[32 + 4 * q] = v.x; r[33 + 4 * q] = v.y; r[34 + 4 * q] = v.z; r[35 + 4 * q] = v.w;
            }
            // edge features (fp32 exact)
            float4 q0 = *(const float4*)(z_h + (size_t)sN * 64);
            float4 q1 = *(const float4*)(z_h + (size_t)sN * 64 + 4);
            float4 r0 = *(const float4*)(z_h + (size_t)tN * 64);
            float4 r1 = *(const float4*)(z_h + (size_t)tN * 64 + 4);
            float dx = q0.x - r0.x, dy = q0.y - r0.y, dz = q0.z - r0.z;
            float dist = dx * dx + dy * dy + dz * dz;
            float cx = q1.x * r1.y - q1.y * r1.x;
            float cy = q1.y * r0.w - q0.w * r1.y;
            float cz = q0.w * r1.x - q1.x * r0.w;
            float cn = sqrtf(cx * cx + cy * cy + cz * cz);
            r[64] = pack_hi(dx, dy);
            r[65] = pack_hi(dz, dist);
            r[66] = pack_hi(cx, cy);
            r[67] = pack_hi(cz, cn);
            r[68] = 0; r[69] = 0; r[70] = 0; r[71] = 0;
        }
        __syncthreads();

        // ---- A1 fragments: 9 kt x 8 regs (M=32: 2 m16 blocks) ----
        uint32_t a1h[72];
        {
            const int r0w = (w * 32 + grp) * ASTR + qid;
#pragma unroll
            for (int kt = 0; kt < 9; kt++) {
                int b0 = r0w + kt * 8;
                a1h[kt * 8 + 0] = smw[E_ACT + b0];
                a1h[kt * 8 + 1] = smw[E_ACT + b0 + 8 * ASTR];
                a1h[kt * 8 + 2] = smw[E_ACT + b0 + 4];
                a1h[kt * 8 + 3] = smw[E_ACT + b0 + 8 * ASTR + 4];
                a1h[kt * 8 + 4] = smw[E_ACT + b0 + 16 * ASTR];
                a1h[kt * 8 + 5] = smw[E_ACT + b0 + 24 * ASTR];
                a1h[kt * 8 + 6] = smw[E_ACT + b0 + 16 * ASTR + 4];
                a1h[kt * 8 + 7] = smw[E_ACT + b0 + 24 * ASTR + 4];
            }
        }
        __syncthreads();

        const int rowbase = (w * 32 + grp) * ASTR;

        // ---- GEMM1 message (1-term): hid = relu(A @ We1 + be1) ----
#pragma unroll
        for (int nt = 0; nt < 16; nt++) {
            float c0[4] = {0.f, 0.f, 0.f, 0.f};
            float c1[4] = {0.f, 0.f, 0.f, 0.f};
            const int base = nt * 8 * WSTR + bq;
#pragma unroll
            for (int kt = 0; kt < 9; kt++) {
                int o = base + kt * 8;
                uint32_t b0 = smw[E_W1E + o], b1 = smw[E_W1E + o + 4];
                MMA_BF16(c0, a1h[kt*8+0], a1h[kt*8+1], a1h[kt*8+2], a1h[kt*8+3], b0, b1);
                MMA_BF16(c1, a1h[kt*8+4], a1h[kt*8+5], a1h[kt*8+6], a1h[kt*8+7], b0, b1);
            }
            const int n0 = nt * 8 + 2 * qid;
            const float be0 = smf[E_BE1 + n0], be1v = smf[E_BE1 + n0 + 1];
            const int wi = rowbase + nt * 4 + qid;
            smw[E_ACT + wi] =
                pack_hi(fmaxf(c0[0] + be0, 0.f), fmaxf(c0[1] + be1v, 0.f));
            smw[E_ACT + wi + 8 * ASTR] =
                pack_hi(fmaxf(c0[2] + be0, 0.f), fmaxf(c0[3] + be1v, 0.f));
            smw[E_ACT + wi + 16 * ASTR] =
                pack_hi(fmaxf(c1[0] + be0, 0.f), fmaxf(c1[1] + be1v, 0.f));
            smw[E_ACT + wi + 24 * ASTR] =
                pack_hi(fmaxf(c1[2] + be0, 0.f), fmaxf(c1[3] + be1v, 0.f));
        }

        // ---- GEMM1 gate (1-term) + fold dot(Wg2) ----
        float ps[4] = {0.f, 0.f, 0.f, 0.f};
#pragma unroll
        for (int nt = 0; nt < 16; nt++) {
            float c0[4] = {0.f, 0.f, 0.f, 0.f};
            float c1[4] = {0.f, 0.f, 0.f, 0.f};
            const int base = nt * 8 * WSTR + bq;
#pragma unroll
            for (int kt = 0; kt < 9; kt++) {
                int o = base + kt * 8;
                uint32_t b0 = smw[E_W1G + o], b1 = smw[E_W1G + o + 4];
                MMA_BF16(c0, a1h[kt*8+0], a1h[kt*8+1], a1h[kt*8+2], a1h[kt*8+3], b0, b1);
                MMA_BF16(c1, a1h[kt*8+4], a1h[kt*8+5], a1h[kt*8+6], a1h[kt*8+7], b0, b1);
            }
            const int n0 = nt * 8 + 2 * qid;
            const float w0 = smf[E_WG2 + n0], w1 = smf[E_WG2 + n0 + 1];
            const float b0v = smf[E_BG1 + n0], b1v = smf[E_BG1 + n0 + 1];
            ps[0] += fmaxf(c0[0] + b0v, 0.f) * w0 + fmaxf(c0[1] + b1v, 0.f) * w1;
            ps[1] += fmaxf(c0[2] + b0v, 0.f) * w0 + fmaxf(c0[3] + b1v, 0.f) * w1;
            ps[2] += fmaxf(c1[0] + b0v, 0.f) * w0 + fmaxf(c1[1] + b1v, 0.f) * w1;
            ps[3] += fmaxf(c1[2] + b0v, 0.f) * w0 + fmaxf(c1[3] + b1v, 0.f) * w1;
        }
#pragma unroll
        for (int i = 0; i < 4; i++) {
            ps[i] += __shfl_xor_sync(0xffffffffu, ps[i], 1);
            ps[i] += __shfl_xor_sync(0xffffffffu, ps[i], 2);
        }
        if (qid == 0) {
            const int gb = w * 32 + grp;
            smf[E_GATE + gb]      = 1.f / (1.f + __expf(-(ps[0] + bg2v)));
            smf[E_GATE + gb + 8]  = 1.f / (1.f + __expf(-(ps[1] + bg2v)));
            smf[E_GATE + gb + 16] = 1.f / (1.f + __expf(-(ps[2] + bg2v)));
            smf[E_GATE + gb + 24] = 1.f / (1.f + __expf(-(ps[3] + bg2v)));
        }
        __syncwarp();

        // ---- A2 fragments (hid, 8 kt x 8 regs) ----
        uint32_t a2h[64];
        {
            const int r0w = rowbase + qid;
#pragma unroll
            for (int kt = 0; kt < 8; kt++) {
                int b0 = r0w + kt * 8;
                a2h[kt * 8 + 0] = smw[E_ACT + b0];
                a2h[kt * 8 + 1] = smw[E_ACT + b0 + 8 * ASTR];
                a2h[kt * 8 + 2] = smw[E_ACT + b0 + 4];
                a2h[kt * 8 + 3] = smw[E_ACT + b0 + 8 * ASTR + 4];
                a2h[kt * 8 + 4] = smw[E_ACT + b0 + 16 * ASTR];
                a2h[kt * 8 + 5] = smw[E_ACT + b0 + 24 * ASTR];
                a2h[kt * 8 + 6] = smw[E_ACT + b0 + 16 * ASTR + 4];
                a2h[kt * 8 + 7] = smw[E_ACT + b0 + 24 * ASTR + 4];
            }
        }
        const int row0 = w * 32 + grp;
        const float g0 = smf[E_GATE + row0];
        const float g1 = smf[E_GATE + row0 + 8];
        const float g2 = smf[E_GATE + row0 + 16];
        const float g3 = smf[E_GATE + row0 + 24];
        const int eg0 = tile * ETILE + row0;
        const int tg0 = smi[E_TGT + row0];
        const int tg1 = smi[E_TGT + row0 + 8];
        const int tg2 = smi[E_TGT + row0 + 16];
        const int tg3 = smi[E_TGT + row0 + 24];

        // ---- GEMM2 (1-term) + scatter gate*(m+be2) ----
#pragma unroll
        for (int nt = 0; nt < 8; nt++) {
            float c0[4] = {0.f, 0.f, 0.f, 0.f};
            float c1[4] = {0.f, 0.f, 0.f, 0.f};
            const int base = nt * 8 * WSTR + bq;
#pragma unroll
            for (int kt = 0; kt < 8; kt++) {
                int o = base + kt * 8;
                uint32_t b0 = smw[E_W2 + o], b1 = smw[E_W2 + o + 4];
                MMA_BF16(c0, a2h[kt*8+0], a2h[kt*8+1], a2h[kt*8+2], a2h[kt*8+3], b0, b1);
                MMA_BF16(c1, a2h[kt*8+4], a2h[kt*8+5], a2h[kt*8+6], a2h[kt*8+7], b0, b1);
            }
            const int n0 = nt * 8 + 2 * qid;
            const float b0v = smf[E_BE2 + n0], b1v = smf[E_BE2 + n0 + 1];
            if (eg0 < E) {
                atomicAdd(g_magg + (size_t)tg0 * 64 + n0,     g0 * (c0[0] + b0v));
                atomicAdd(g_magg + (size_t)tg0 * 64 + n0 + 1, g0 * (c0[1] + b1v));
            }
            if (eg0 + 8 < E) {
                atomicAdd(g_magg + (size_t)tg1 * 64 + n0,     g1 * (c0[2] + b0v));
                atomicAdd(g_magg + (size_t)tg1 * 64 + n0 + 1, g1 * (c0[3] + b1v));
            }
            if (eg0 + 16 < E) {
                atomicAdd(g_magg + (size_t)tg2 * 64 + n0,     g2 * (c1[0] + b0v));
                atomicAdd(g_magg + (size_t)tg2 * 64 + n0 + 1, g2 * (c1[1] + b1v));
            }
            if (eg0 + 24 < E) {
                atomicAdd(g_magg + (size_t)tg3 * 64 + n0,     g3 * (c1[2] + b0v));
                atomicAdd(g_magg + (size_t)tg3 * 64 + n0 + 1, g3 * (c1[3] + b1v));
            }
        }
        __syncthreads();
    }
}

// ===========================================================================
// NODE kernel: MMA 3-term (precision-critical) — unchanged from R5
// ===========================================================================
#define N_W1_HI 0
#define N_W1_LO 8704
#define N_W2_HI 17408
#define N_W2_LO 21760
#define N_ACT_H 26112
#define N_ACT_L 35840
#define N_BN1   45568
#define N_WS    45696
#define N_WORDS 45760
#define N_BYTES (N_WORDS * 4)

__global__ void __launch_bounds__(256, 1)
node_mma_kernel(const float* __restrict__ z_h,
                const float* __restrict__ Wn1, const float* __restrict__ bn1,
                const float* __restrict__ Wn2, const float* __restrict__ bn2,
                float* __restrict__ out, int N) {
    extern __shared__ uint32_t smw[];
    float* smf = (float*)smw;
    uint16_t* smh = (uint16_t*)smw;

    const int t = threadIdx.x;
    const int w = t >> 5;
    const int l = t & 31;
    const int grp = l >> 2;
    const int qid = l & 3;

    for (int idx = t; idx < 128 * 128; idx += 256) {
        int k = idx >> 7, n = idx & 127;
        float v = Wn1[idx];
        __nv_bfloat16 h = __float2bfloat16(v);
        float r = v - __bfloat162float(h);
        smh[(N_W1_HI + n * WSTR) * 2 + k] = __bfloat16_as_ushort(h);
        smh[(N_W1_LO + n * WSTR) * 2 + k] = __bfloat16_as_ushort(__float2bfloat16(r));
    }
    for (int idx = t; idx < 128 * 64; idx += 256) {
        int k = idx >> 6, n = idx & 63;
        float v = Wn2[idx];
        __nv_bfloat16 h = __float2bfloat16(v);
        float r = v - __bfloat162float(h);
        smh[(N_W2_HI + n * WSTR) * 2 + k] = __bfloat16_as_ushort(h);
        smh[(N_W2_LO + n * WSTR) * 2 + k] = __bfloat16_as_ushort(__float2bfloat16(r));
    }
    if (t < 128) smf[N_BN1 + t] = bn1[t];
    if (t < 64) smf[N_WS + t] = g_wsum[t];
    __syncthreads();

    const int ntiles = (N + 127) / 128;
    const int bq = grp * WSTR + qid;

    for (int tile = blockIdx.x; tile < ntiles; tile += gridDim.x) {
        {
            int e = t >> 1, half = t & 1;
            int n = tile * 128 + e;
            bool v = (n < N);
            const float4* srcp = half
                ? (const float4*)(g_magg + (size_t)(v ? n : 0) * 64)
                : (const float4*)(z_h + (size_t)(v ? n : 0) * 64);
            const float4* wsp = (const float4*)(smf + N_WS);
            uint32_t* rh = smw + N_ACT_H + e * ASTR + half * 32;
            uint32_t* rl = smw + N_ACT_L + e * ASTR + half * 32;
#pragma unroll
            for (int q = 0; q < 16; q++) {
                float4 x = srcp[q];
                if (half) {
                    float4 ws = wsp[q];
                    x.x += ws.x; x.y += ws.y; x.z += ws.z; x.w += ws.w;
                }
                if (!v) x = make_float4(0.f, 0.f, 0.f, 0.f);
                uint32_t h0, l0, h1, l1;
                pack_pair(x.x, x.y, h0, l0);
                pack_pair(x.z, x.w, h1, l1);
                rh[2 * q] = h0; rh[2 * q + 1] = h1;
                rl[2 * q] = l0; rl[2 * q + 1] = l1;
            }
        }
        __syncthreads();

        uint32_t a1h[32], a1l[32];
        {
            const int r0w = (w * 16 + grp) * ASTR + qid;
#pragma unroll
            for (int kt = 0; kt < 8; kt++) {
                int b0 = r0w + kt * 8;
                a1h[kt * 4 + 0] = smw[N_ACT_H + b0];
                a1h[kt * 4 + 1] = smw[N_ACT_H + b0 + 8 * ASTR];
                a1h[kt * 4 + 2] = smw[N_ACT_H + b0 + 4];
                a1h[kt * 4 + 3] = smw[N_ACT_H + b0 + 8 * ASTR + 4];
                a1l[kt * 4 + 0] = smw[N_ACT_L + b0];
                a1l[kt * 4 + 1] = smw[N_ACT_L + b0 + 8 * ASTR];
                a1l[kt * 4 + 2] = smw[N_ACT_L + b0 + 4];
                a1l[kt * 4 + 3] = smw[N_ACT_L + b0 + 8 * ASTR + 4];
            }
        }
        __syncthreads();

        const int rowbase = (w * 16 + grp) * ASTR;

#pragma unroll
        for (int nt = 0; nt < 16; nt++) {
            float c[4] = {0.f, 0.f, 0.f, 0.f};
            const int base = nt * 8 * WSTR + bq;
#pragma unroll
            for (int kt = 0; kt < 8; kt++) {
                int o = base + kt * 8;
                uint32_t bh0 = smw[N_W1_HI + o], bh1 = smw[N_W1_HI + o + 4];
                uint32_t bl0 = smw[N_W1_LO + o], bl1 = smw[N_W1_LO + o + 4];
                MMA_BF16(c, a1h[kt*4], a1h[kt*4+1], a1h[kt*4+2], a1h[kt*4+3], bh0, bh1);
                MMA_BF16(c, a1l[kt*4], a1l[kt*4+1], a1l[kt*4+2], a1l[kt*4+3], bh0, bh1);
                MMA_BF16(c, a1h[kt*4], a1h[kt*4+1], a1h[kt*4+2], a1h[kt*4+3], bl0, bl1);
            }
            int n0 = nt * 8 + 2 * qid;
            float v0 = fmaxf(c[0] + smf[N_BN1 + n0], 0.f);
            float v1 = fmaxf(c[1] + smf[N_BN1 + n0 + 1], 0.f);
            float v2 = fmaxf(c[2] + smf[N_BN1 + n0], 0.f);
            float v3 = fmaxf(c[3] + smf[N_BN1 + n0 + 1], 0.f);
            uint32_t h0, l0, h1, l1;
            pack_pair(v0, v1, h0, l0);
            pack_pair(v2, v3, h1, l1);
            int wi = rowbase + nt * 4 + qid;
            smw[N_ACT_H + wi] = h0;
            smw[N_ACT_L + wi] = l0;
            smw[N_ACT_H + wi + 8 * ASTR] = h1;
            smw[N_ACT_L + wi + 8 * ASTR] = l1;
        }

        uint32_t a2h[32], a2l[32];
        {
            const int r0w = rowbase + qid;
#pragma unroll
            for (int kt = 0; kt < 8; kt++) {
                int b0 = r0w + kt * 8;
                a2h[kt * 4 + 0] = smw[N_ACT_H + b0];
                a2h[kt * 4 + 1] = smw[N_ACT_H + b0 + 8 * ASTR];
                a2h[kt * 4 + 2] = smw[N_ACT_H + b0 + 4];
                a2h[kt * 4 + 3] = smw[N_ACT_H + b0 + 8 * ASTR + 4];
                a2l[kt * 4 + 0] = smw[N_ACT_L + b0];
                a2l[kt * 4 + 1] = smw[N_ACT_L + b0 + 8 * ASTR];
                a2l[kt * 4 + 2] = smw[N_ACT_L + b0 + 4];
                a2l[kt * 4 + 3] = smw[N_ACT_L + b0 + 8 * ASTR + 4];
            }
        }
        const int r0 = tile * 128 + w * 16 + grp;
        const int r1 = r0 + 8;

#pragma unroll
        for (int nt = 0; nt < 8; nt++) {
            float c[4] = {0.f, 0.f, 0.f, 0.f};
            const int base = nt * 8 * WSTR + bq;
#pragma unroll
            for (int kt = 0; kt < 8; kt++) {
                int o = base + kt * 8;
                uint32_t bh0 = smw[N_W2_HI + o], bh1 = smw[N_W2_HI + o + 4];
                uint32_t bl0 = smw[N_W2_LO + o], bl1 = smw[N_W2_LO + o + 4];
                MMA_BF16(c, a2h[kt*4], a2h[kt*4+1], a2h[kt*4+2], a2h[kt*4+3], bh0, bh1);
                MMA_BF16(c, a2l[kt*4], a2l[kt*4+1], a2l[kt*4+2], a2l[kt*4+3], bh0, bh1);
                MMA_BF16(c, a2h[kt*4], a2h[kt*4+1], a2h[kt*4+2], a2h[kt*4+3], bl0, bl1);
            }
            int n0 = nt * 8 + 2 * qid;
            float b0v = __ldg(&bn2[n0]), b1v = __ldg(&bn2[n0 + 1]);
            if (r0 < N) {
                float2 o2 = make_float2(c[0] + b0v, c[1] + b1v);
                *(float2*)(out + (size_t)r0 * 64 + n0) = o2;
            }
            if (r1 < N) {
                float2 o2 = make_float2(c[2] + b0v, c[3] + b1v);
                *(float2*)(out + (size_t)r1 * 64 + n0) = o2;
            }
        }
        __syncthreads();
    }
}

// ===========================================================================
// WORLD kernel: MMA 3-term — unchanged from R5
// ===========================================================================
#define W_W1_HI 0
#define W_W1_LO 8704
#define W_W2_HI 17408
#define W_W2_LO 21760
#define W_ACT_H 26112
#define W_ACT_L 35840
#define W_BW1   45568
#define W_RED   45696
#define W_WORDS 46208
#define W_BYTES (W_WORDS * 4)

__global__ void __launch_bounds__(256, 1)
world_mma_kernel(const float* __restrict__ z_h, const float* __restrict__ pos_world,
                 const float* __restrict__ Ww1, const float* __restrict__ bw1,
                 const float* __restrict__ Ww2, int N) {
    extern __shared__ uint32_t smw[];
    float* smf = (float*)smw;
    uint16_t* smh = (uint16_t*)smw;

    const int t = threadIdx.x;
    const int w = t >> 5;
    const int l = t & 31;
    const int grp = l >> 2;
    const int qid = l & 3;

    for (int i = t; i < 17408; i += 256) smw[W_W1_HI + i] = 0;
    __syncthreads();
    for (int idx = t; idx < 67 * 128; idx += 256) {
        int k = idx >> 7, n = idx & 127;
        float v = Ww1[idx];
        __nv_bfloat16 h = __float2bfloat16(v);
        float r = v - __bfloat162float(h);
        smh[(W_W1_HI + n * WSTR) * 2 + k] = __bfloat16_as_ushort(h);
        smh[(W_W1_LO + n * WSTR) * 2 + k] = __bfloat16_as_ushort(__float2bfloat16(r));
    }
    for (int idx = t; idx < 128 * 64; idx += 256) {
        int k = idx >> 6, n = idx & 63;
        float v = Ww2[idx];
        __nv_bfloat16 h = __float2bfloat16(v);
        float r = v - __bfloat162float(h);
        smh[(W_W2_HI + n * WSTR) * 2 + k] = __bfloat16_as_ushort(h);
        smh[(W_W2_LO + n * WSTR) * 2 + k] = __bfloat16_as_ushort(__float2bfloat16(r));
    }
    if (t < 128) smf[W_BW1 + t] = bw1[t];
    const float p0 = __ldg(&pos_world[0]);
    const float p1 = __ldg(&pos_world[1]);
    const float p2 = __ldg(&pos_world[2]);
    __syncthreads();

    const int ntiles = (N + 127) / 128;
    const int bq = grp * WSTR + qid;

    float accs[16];
#pragma unroll
    for (int i = 0; i < 16; i++) accs[i] = 0.f;

    for (int tile = blockIdx.x; tile < ntiles; tile += gridDim.x) {
        {
            int e = t >> 1, half = t & 1;
            int n = tile * 128 + e;
            bool v = (n < N);
            const float4* zp = (const float4*)(z_h + (size_t)(v ? n : 0) * 64) + half * 8;
            uint32_t* rh = smw + W_ACT_H + e * ASTR + half * 16;
            uint32_t* rl = smw + W_ACT_L + e * ASTR + half * 16;
#pragma unroll
            for (int q = 0; q < 8; q++) {
                float4 x = zp[q];
                if (!v) x = make_float4(0.f, 0.f, 0.f, 0.f);
                uint32_t h0, l0, h1, l1;
                pack_pair(x.x, x.y, h0, l0);
                pack_pair(x.z, x.w, h1, l1);
                rh[2 * q] = h0; rh[2 * q + 1] = h1;
                rl[2 * q] = l0; rl[2 * q + 1] = l1;
            }
        }
        if (t < 128) {
            int n = tile * 128 + t;
            bool v = (n < N);
            float4 z0 = *(const float4*)(z_h + (size_t)(v ? n : 0) * 64);
            float d0 = v ? z0.x - p0 : 0.f;
            float d1 = v ? z0.y - p1 : 0.f;
            float d2 = v ? z0.z - p2 : 0.f;
            uint32_t* rh = smw + W_ACT_H + t * ASTR + 32;
            uint32_t* rl = smw + W_ACT_L + t * ASTR + 32;
            uint32_t h0, l0, h1, l1;
            pack_pair(d0, d1, h0, l0);
            pack_pair(d2, 0.f, h1, l1);
            rh[0] = h0; rl[0] = l0;
            rh[1] = h1; rl[1] = l1;
#pragma unroll
            for (int q = 2; q < 8; q++) { rh[q] = 0; rl[q] = 0; }
        }
        __syncthreads();

        uint32_t a1h[20], a1l[20];
        {
            const int r0w = (w * 16 + grp) * ASTR + qid;
#pragma unroll
            for (int kt = 0; kt < 5; kt++) {
                int b0 = r0w + kt * 8;
                a1h[kt * 4 + 0] = smw[W_ACT_H + b0];
                a1h[kt * 4 + 1] = smw[W_ACT_H + b0 + 8 * ASTR];
                a1h[kt * 4 + 2] = smw[W_ACT_H + b0 + 4];
                a1h[kt * 4 + 3] = smw[W_ACT_H + b0 + 8 * ASTR + 4];
                a1l[kt * 4 + 0] = smw[W_ACT_L + b0];
                a1l[kt * 4 + 1] = smw[W_ACT_L + b0 + 8 * ASTR];
                a1l[kt * 4 + 2] = smw[W_ACT_L + b0 + 4];
                a1l[kt * 4 + 3] = smw[W_ACT_L + b0 + 8 * ASTR + 4];
            }
        }
        __syncthreads();

        const int rowbase = (w * 16 + grp) * ASTR;

#pragma unroll
        for (int nt = 0; nt < 16; nt++) {
            float c[4] = {0.f, 0.f, 0.f, 0.f};
            const int base = nt * 8 * WSTR + bq;
#pragma unroll
            for (int kt = 0; kt < 5; kt++) {
                int o = base + kt * 8;
                uint32_t bh0 = smw[W_W1_HI + o], bh1 = smw[W_W1_HI + o + 4];
                uint32_t bl0 = smw[W_W1_LO + o], bl1 = smw[W_W1_LO + o + 4];
                MMA_BF16(c, a1h[kt*4], a1h[kt*4+1], a1h[kt*4+2], a1h[kt*4+3], bh0, bh1);
                MMA_BF16(c, a1l[kt*4], a1l[kt*4+1], a1l[kt*4+2], a1l[kt*4+3], bh0, bh1);
                MMA_BF16(c, a1h[kt*4], a1h[kt*4+1], a1h[kt*4+2], a1h[kt*4+3], bl0, bl1);
            }
            int n0 = nt * 8 + 2 * qid;
            float v0 = fmaxf(c[0] + smf[W_BW1 + n0], 0.f);
            float v1 = fmaxf(c[1] + smf[W_BW1 + n0 + 1], 0.f);
            float v2 = fmaxf(c[2] + smf[W_BW1 + n0], 0.f);
            float v3 = fmaxf(c[3] + smf[W_BW1 + n0 + 1], 0.f);
            uint32_t h0, l0, h1, l1;
            pack_pair(v0, v1, h0, l0);
            pack_pair(v2, v3, h1, l1);
            int wi = rowbase + nt * 4 + qid;
            smw[W_ACT_H + wi] = h0;
            smw[W_ACT_L + wi] = l0;
            smw[W_ACT_H + wi + 8 * ASTR] = h1;
            smw[W_ACT_L + wi + 8 * ASTR] = l1;
        }

        uint32_t a2h[32], a2l[32];
        {
            const int r0w = rowbase + qid;
#pragma unroll
            for (int kt = 0; kt < 8; kt++) {
                int b0 = r0w + kt * 8;
                a2h[kt * 4 + 0] = smw[W_ACT_H + b0];
                a2h[kt * 4 + 1] = smw[W_ACT_H + b0 + 8 * ASTR];
                a2h[kt * 4 + 2] = smw[W_ACT_H + b0 + 4];
                a2h[kt * 4 + 3] = smw[W_ACT_H + b0 + 8 * ASTR + 4];
                a2l[kt * 4 + 0] = smw[W_ACT_L + b0];
                a2l[kt * 4 + 1] = smw[W_ACT_L + b0 + 8 * ASTR];
                a2l[kt * 4 + 2] = smw[W_ACT_L + b0 + 4];
                a2l[kt * 4 + 3] = smw[W_ACT_L + b0 + 8 * ASTR + 4];
            }
        }
        const int r0 = tile * 128 + w * 16 + grp;
        const float m0 = (r0 < N) ? 1.f : 0.f;
        const float m1 = (r0 + 8 < N) ? 1.f : 0.f;

#pragma unroll
        for (int nt = 0; nt < 8; nt++) {
            float c[4] = {0.f, 0.f, 0.f, 0.f};
            const int base = nt * 8 * WSTR + bq;
#pragma unroll
            for (int kt = 0; kt < 8; kt++) {
                int o = base + kt * 8;
                uint32_t bh0 = smw[W_W2_HI + o], bh1 = smw[W_W2_HI + o + 4];
                uint32_t bl0 = smw[W_W2_LO + o], bl1 = smw[W_W2_LO + o + 4];
                MMA_BF16(c, a2h[kt*4], a2h[kt*4+1], a2h[kt*4+2], a2h[kt*4+3], bh0, bh1);
                MMA_BF16(c, a2l[kt*4], a2l[kt*4+1], a2l[kt*4+2], a2l[kt*4+3], bh0, bh1);
                MMA_BF16(c, a2h[kt*4], a2h[kt*4+1], a2h[kt*4+2], a2h[kt*4+3], bl0, bl1);
            }
            accs[nt * 2]     += m0 * c[0] + m1 * c[2];
            accs[nt * 2 + 1] += m0 * c[1] + m1 * c[3];
        }
        __syncthreads();
    }

#pragma unroll
    for (int i = 0; i < 16; i++) {
        accs[i] += __shfl_xor_sync(0xffffffffu, accs[i], 4);
        accs[i] += __shfl_xor_sync(0xffffffffu, accs[i], 8);
        accs[i] += __shfl_xor_sync(0xffffffffu, accs[i], 16);
    }
    if (l < 4) {
#pragma unroll
        for (int nt = 0; nt < 8; nt++) {
            smf[W_RED + w * 64 + nt * 8 + 2 * l]     = accs[nt * 2];
            smf[W_RED + w * 64 + nt * 8 + 2 * l + 1] = accs[nt * 2 + 1];
        }
    }
    __syncthreads();
    if (t < 64) {
        float s = 0.f;
#pragma unroll
        for (int ww = 0; ww < 8; ww++) s += smf[W_RED + ww * 64 + t];
        atomicAdd(&g_wsum[t], s);
    }
}

// ===========================================================================
extern "C" void kernel_launch(void* const* d_in, const int* in_sizes, int n_in,
                              void* d_out, int out_size) {
    const float* z_h       = (const float*)d_in[0];
    const float* pos_world = (const float*)d_in[1];
    const int*   ei        = (const int*)d_in[2];
    const float* We1 = (const float*)d_in[3];
    const float* be1 = (const float*)d_in[4];
    const float* We2 = (const float*)d_in[5];
    const float* be2 = (const float*)d_in[6];
    const float* Wg1 = (const float*)d_in[7];
    const float* bg1 = (const float*)d_in[8];
    const float* Wg2 = (const float*)d_in[9];
    const float* bg2 = (const float*)d_in[10];
    const float* Wn1 = (const float*)d_in[11];
    const float* bn1 = (const float*)d_in[12];
    const float* Wn2 = (const float*)d_in[13];
    const float* bn2 = (const float*)d_in[14];
    const float* Ww1 = (const float*)d_in[15];
    const float* bw1 = (const float*)d_in[16];
    const float* Ww2 = (const float*)d_in[17];
    const float* bw2 = (const float*)d_in[18];

    const int N = in_sizes[0] / 64;
    const int E = in_sizes[2] / 2;
    float* out = (float*)d_out;

    cudaFuncSetAttribute(edge_mma_kernel,
                         cudaFuncAttributeMaxDynamicSharedMemorySize, E_BYTES);
    cudaFuncSetAttribute(node_mma_kernel,
                         cudaFuncAttributeMaxDynamicSharedMemorySize, N_BYTES);
    cudaFuncSetAttribute(world_mma_kernel,
                         cudaFuncAttributeMaxDynamicSharedMemorySize, W_BYTES);

    const int total = N * 64;
    zero_kernel<<<(total + 255) / 256, 256>>>(total, bw2, (float)N);
    prepack_kernel<<<(N * 32 + 255) / 256, 256>>>(z_h, N * 32);
    world_mma_kernel<<<148, 256, W_BYTES>>>(z_h, pos_world, Ww1, bw1, Ww2, N);
    edge_mma_kernel<<<148, ETHREADS, E_BYTES>>>(z_h, ei, We1, be1, We2, be2,
                                                Wg1, bg1, Wg2, bg2, E);
    node_mma_kernel<<<148, 256, N_BYTES>>>(z_h, Wn1, bn1, Wn2, bn2, out, N);
}

// round 7
// speedup vs baseline: 9.2545x; 1.2313x over previous
#include <cuda_runtime.h>
#include <cuda_bf16.h>
#include <math.h>
#include <stdint.h>

// ===========================================================================
// Scratch (no allocations allowed)
// ===========================================================================
__device__ float g_magg[50048 * 64];
__device__ float g_wsum[64];
__device__ uint32_t g_zpk[50048 * 32];   // prepacked bf16x2 z_h

// ===========================================================================
// warp MMA m16n8k16 bf16 (sm_80+ PTX, no arch suffix)
// ===========================================================================
#define MMA_BF16(c, a0, a1, a2, a3, b0, b1) \
    asm volatile("mma.sync.aligned.m16n8k16.row.col.f32.bf16.bf16.f32 " \
        "{%0,%1,%2,%3},{%4,%5,%6,%7},{%8,%9},{%0,%1,%2,%3};" \
        : "+f"((c)[0]), "+f"((c)[1]), "+f"((c)[2]), "+f"((c)[3]) \
        : "r"(a0), "r"(a1), "r"(a2), "r"(a3), "r"(b0), "r"(b1))

__device__ __forceinline__ uint32_t pack_hi(float v0, float v1) {
    return ((uint32_t)__bfloat16_as_ushort(__float2bfloat16(v1)) << 16) |
           (uint32_t)__bfloat16_as_ushort(__float2bfloat16(v0));
}

__device__ __forceinline__ void pack_pair(float v0, float v1, uint32_t& hi, uint32_t& lo) {
    __nv_bfloat16 h0 = __float2bfloat16(v0);
    __nv_bfloat16 h1 = __float2bfloat16(v1);
    float r0 = v0 - __bfloat162float(h0);
    float r1 = v1 - __bfloat162float(h1);
    hi = ((uint32_t)__bfloat16_as_ushort(h1) << 16) | (uint32_t)__bfloat16_as_ushort(h0);
    lo = ((uint32_t)__bfloat16_as_ushort(__float2bfloat16(r1)) << 16) |
         (uint32_t)__bfloat16_as_ushort(__float2bfloat16(r0));
}

__device__ __forceinline__ float bf_lo(uint32_t u) {
    return __bfloat162float(__ushort_as_bfloat16((unsigned short)(u & 0xffffu)));
}
__device__ __forceinline__ float bf_hi(uint32_t u) {
    return __bfloat162float(__ushort_as_bfloat16((unsigned short)(u >> 16)));
}

#define ASTR 76   // activation row stride, words (mod32=12, conflict-free)
#define WSTR 68   // weight row stride, words (mod32=4, conflict-free)

// ===========================================================================
// prepack: z_h fp32 -> packed bf16x2
// ===========================================================================
__global__ void prepack_kernel(const float* __restrict__ z_h, int nwords) {
    int i = blockIdx.x * blockDim.x + threadIdx.x;
    if (i < nwords) {
        float2 v = ((const float2*)z_h)[i];
        g_zpk[i] = pack_hi(v.x, v.y);
    }
}

// ===========================================================================
// zero/init: g_magg = 0, g_wsum = N * bw2 (world bias folded in)
// ===========================================================================
__global__ void zero_kernel(int total, const float* __restrict__ bw2, float Nf) {
    int i = blockIdx.x * blockDim.x + threadIdx.x;
    if (i < total) g_magg[i] = 0.f;
    if (i < 64) g_wsum[i] = Nf * bw2[i];
}

// ===========================================================================
// EDGE kernel: 12 warps, each warp independently processes 32-edge units.
// All weights 1-term bf16. No block barriers inside the work loop.
// ===========================================================================
#define ETHREADS 384
#define EWARPS   12

#define E_W1E   0                    // 128*68 = 8704 words
#define E_W1G   8704
#define E_W2    17408                // 64*68 = 4352 words
#define E_ACT   21760                // 384*76 = 29184 words
#define E_TGT   50944                // 384
#define E_GATE  51328                // 384
#define E_BE1   51712
#define E_BG1   51840
#define E_WG2   51968
#define E_BE2   52096
#define E_WORDS 52160
#define E_BYTES (E_WORDS * 4)        // 208640

__global__ void __launch_bounds__(ETHREADS, 1)
edge_mma_kernel(const int* __restrict__ ei,
                const float* __restrict__ We1, const float* __restrict__ be1,
                const float* __restrict__ We2, const float* __restrict__ be2,
                const float* __restrict__ Wg1, const float* __restrict__ bg1,
                const float* __restrict__ Wg2, const float* __restrict__ bg2,
                int E) {
    extern __shared__ uint32_t smw[];
    float* smf = (float*)smw;
    int* smi = (int*)smw;
    uint16_t* smh = (uint16_t*)smw;

    const int t = threadIdx.x;
    const int w = t >> 5;           // warp 0..11
    const int l = t & 31;
    const int grp = l >> 2;         // 0..7
    const int qid = l & 3;          // 0..3

    // ---- stage weights once (1-term bf16), single block barrier ----
    for (int idx = t; idx < 136 * 128; idx += ETHREADS) {
        int k = idx >> 7, n = idx & 127;
        smh[(E_W1E + n * WSTR) * 2 + k] = __bfloat16_as_ushort(__float2bfloat16(We1[idx]));
        smh[(E_W1G + n * WSTR) * 2 + k] = __bfloat16_as_ushort(__float2bfloat16(Wg1[idx]));
    }
    for (int idx = t; idx < 128 * 64; idx += ETHREADS) {
        int k = idx >> 6, n = idx & 63;
        smh[(E_W2 + n * WSTR) * 2 + k] = __bfloat16_as_ushort(__float2bfloat16(We2[idx]));
    }
    if (t < 128) {
        smf[E_BE1 + t] = be1[t];
        smf[E_BG1 + t] = bg1[t];
        smf[E_WG2 + t] = Wg2[t];
    }
    if (t < 64) smf[E_BE2 + t] = be2[t];
    const float bg2v = __ldg(&bg2[0]);
    __syncthreads();

    const int nunits = (E + 31) / 32;
    const int bq = grp * WSTR + qid;
    const int e_local = w * 32 + l;                      // this lane's ACT row
    uint32_t* const myrow = smw + E_ACT + e_local * ASTR;
    const int rowbase = (w * 32 + grp) * ASTR;
    const int row0 = w * 32 + grp;

    for (int unit = blockIdx.x * EWARPS + w; unit < nunits; unit += gridDim.x * EWARPS) {
        // ---- gather: 1 lane per edge, packed bf16 rows ----
        const int eg = unit * 32 + l;
        const int sN = (eg < E) ? ei[eg] : 0;
        const int tN = (eg < E) ? ei[E + eg] : 0;
        smi[E_TGT + e_local] = tN;
        const uint4* zs = (const uint4*)(g_zpk + (size_t)sN * 32);
        const uint4* zt = (const uint4*)(g_zpk + (size_t)tN * 32);
        uint4 s0 = zs[0];
        uint4 t0 = zt[0];
        myrow[0] = s0.x; myrow[1] = s0.y; myrow[2] = s0.z; myrow[3] = s0.w;
        myrow[32] = t0.x; myrow[33] = t0.y; myrow[34] = t0.z; myrow[35] = t0.w;
#pragma unroll
        for (int q = 1; q < 8; q++) {
            uint4 v = zs[q];
            myrow[4 * q] = v.x; myrow[4 * q + 1] = v.y;
            myrow[4 * q + 2] = v.z; myrow[4 * q + 3] = v.w;
        }
#pragma unroll
        for (int q = 1; q < 8; q++) {
            uint4 v = zt[q];
            myrow[32 + 4 * q] = v.x; myrow[33 + 4 * q] = v.y;
            myrow[34 + 4 * q] = v.z; myrow[35 + 4 * q] = v.w;
        }
        // edge features from packed bf16 (validated error budget)
        {
            float a0 = bf_lo(s0.x), a1 = bf_hi(s0.x), a2 = bf_lo(s0.y);
            float a3 = bf_hi(s0.y), a4 = bf_lo(s0.z), a5 = bf_hi(s0.z);
            float b0 = bf_lo(t0.x), b1 = bf_hi(t0.x), b2 = bf_lo(t0.y);
            float b3 = bf_hi(t0.y), b4 = bf_lo(t0.z), b5 = bf_hi(t0.z);
            float dx = a0 - b0, dy = a1 - b1, dz = a2 - b2;
            float dist = dx * dx + dy * dy + dz * dz;
            float cx = a4 * b5 - a5 * b4;
            float cy = a5 * b3 - a3 * b5;
            float cz = a3 * b4 - a4 * b3;
            float cn = sqrtf(cx * cx + cy * cy + cz * cz);
            myrow[64] = pack_hi(dx, dy);
            myrow[65] = pack_hi(dz, dist);
            myrow[66] = pack_hi(cx, cy);
            myrow[67] = pack_hi(cz, cn);
            myrow[68] = 0; myrow[69] = 0; myrow[70] = 0; myrow[71] = 0;
        }
        __syncwarp();

        // ---- A1 fragments: 9 kt x 8 regs (M=32) ----
        uint32_t a1h[72];
        {
            const int r0w = rowbase + qid;
#pragma unroll
            for (int kt = 0; kt < 9; kt++) {
                int b0 = r0w + kt * 8;
                a1h[kt * 8 + 0] = smw[E_ACT + b0];
                a1h[kt * 8 + 1] = smw[E_ACT + b0 + 8 * ASTR];
                a1h[kt * 8 + 2] = smw[E_ACT + b0 + 4];
                a1h[kt * 8 + 3] = smw[E_ACT + b0 + 8 * ASTR + 4];
                a1h[kt * 8 + 4] = smw[E_ACT + b0 + 16 * ASTR];
                a1h[kt * 8 + 5] = smw[E_ACT + b0 + 24 * ASTR];
                a1h[kt * 8 + 6] = smw[E_ACT + b0 + 16 * ASTR + 4];
                a1h[kt * 8 + 7] = smw[E_ACT + b0 + 24 * ASTR + 4];
            }
        }
        __syncwarp();

        // ---- GEMM1 message: hid = relu(A @ We1 + be1) ----
#pragma unroll
        for (int nt = 0; nt < 16; nt++) {
            float c0[4] = {0.f, 0.f, 0.f, 0.f};
            float c1[4] = {0.f, 0.f, 0.f, 0.f};
            const int base = nt * 8 * WSTR + bq;
#pragma unroll
            for (int kt = 0; kt < 9; kt++) {
                int o = base + kt * 8;
                uint32_t b0 = smw[E_W1E + o], b1 = smw[E_W1E + o + 4];
                MMA_BF16(c0, a1h[kt*8+0], a1h[kt*8+1], a1h[kt*8+2], a1h[kt*8+3], b0, b1);
                MMA_BF16(c1, a1h[kt*8+4], a1h[kt*8+5], a1h[kt*8+6], a1h[kt*8+7], b0, b1);
            }
            const int n0 = nt * 8 + 2 * qid;
            const float be0 = smf[E_BE1 + n0], be1v = smf[E_BE1 + n0 + 1];
            const int wi = rowbase + nt * 4 + qid;
            smw[E_ACT + wi] =
                pack_hi(fmaxf(c0[0] + be0, 0.f), fmaxf(c0[1] + be1v, 0.f));
            smw[E_ACT + wi + 8 * ASTR] =
                pack_hi(fmaxf(c0[2] + be0, 0.f), fmaxf(c0[3] + be1v, 0.f));
            smw[E_ACT + wi + 16 * ASTR] =
                pack_hi(fmaxf(c1[0] + be0, 0.f), fmaxf(c1[1] + be1v, 0.f));
            smw[E_ACT + wi + 24 * ASTR] =
                pack_hi(fmaxf(c1[2] + be0, 0.f), fmaxf(c1[3] + be1v, 0.f));
        }

        // ---- GEMM1 gate + fold dot(Wg2) ----
        float ps[4] = {0.f, 0.f, 0.f, 0.f};
#pragma unroll
        for (int nt = 0; nt < 16; nt++) {
            float c0[4] = {0.f, 0.f, 0.f, 0.f};
            float c1[4] = {0.f, 0.f, 0.f, 0.f};
            const int base = nt * 8 * WSTR + bq;
#pragma unroll
            for (int kt = 0; kt < 9; kt++) {
                int o = base + kt * 8;
                uint32_t b0 = smw[E_W1G + o], b1 = smw[E_W1G + o + 4];
                MMA_BF16(c0, a1h[kt*8+0], a1h[kt*8+1], a1h[kt*8+2], a1h[kt*8+3], b0, b1);
                MMA_BF16(c1, a1h[kt*8+4], a1h[kt*8+5], a1h[kt*8+6], a1h[kt*8+7], b0, b1);
            }
            const int n0 = nt * 8 + 2 * qid;
            const float w0 = smf[E_WG2 + n0], w1 = smf[E_WG2 + n0 + 1];
            const float b0v = smf[E_BG1 + n0], b1v = smf[E_BG1 + n0 + 1];
            ps[0] += fmaxf(c0[0] + b0v, 0.f) * w0 + fmaxf(c0[1] + b1v, 0.f) * w1;
            ps[1] += fmaxf(c0[2] + b0v, 0.f) * w0 + fmaxf(c0[3] + b1v, 0.f) * w1;
            ps[2] += fmaxf(c1[0] + b0v, 0.f) * w0 + fmaxf(c1[1] + b1v, 0.f) * w1;
            ps[3] += fmaxf(c1[2] + b0v, 0.f) * w0 + fmaxf(c1[3] + b1v, 0.f) * w1;
        }
#pragma unroll
        for (int i = 0; i < 4; i++) {
            ps[i] += __shfl_xor_sync(0xffffffffu, ps[i], 1);
            ps[i] += __shfl_xor_sync(0xffffffffu, ps[i], 2);
        }
        if (qid == 0) {
            smf[E_GATE + row0]      = 1.f / (1.f + __expf(-(ps[0] + bg2v)));
            smf[E_GATE + row0 + 8]  = 1.f / (1.f + __expf(-(ps[1] + bg2v)));
            smf[E_GATE + row0 + 16] = 1.f / (1.f + __expf(-(ps[2] + bg2v)));
            smf[E_GATE + row0 + 24] = 1.f / (1.f + __expf(-(ps[3] + bg2v)));
        }
        __syncwarp();   // hid + gate visible to all lanes of this warp

        // ---- A2 fragments (hid) ----
        uint32_t a2h[64];
        {
            const int r0w = rowbase + qid;
#pragma unroll
            for (int kt = 0; kt < 8; kt++) {
                int b0 = r0w + kt * 8;
                a2h[kt * 8 + 0] = smw[E_ACT + b0];
                a2h[kt * 8 + 1] = smw[E_ACT + b0 + 8 * ASTR];
                a2h[kt * 8 + 2] = smw[E_ACT + b0 + 4];
                a2h[kt * 8 + 3] = smw[E_ACT + b0 + 8 * ASTR + 4];
                a2h[kt * 8 + 4] = smw[E_ACT + b0 + 16 * ASTR];
                a2h[kt * 8 + 5] = smw[E_ACT + b0 + 24 * ASTR];
                a2h[kt * 8 + 6] = smw[E_ACT + b0 + 16 * ASTR + 4];
                a2h[kt * 8 + 7] = smw[E_ACT + b0 + 24 * ASTR + 4];
            }
        }
        const float g0 = smf[E_GATE + row0];
        const float g1 = smf[E_GATE + row0 + 8];
        const float g2 = smf[E_GATE + row0 + 16];
        const float g3 = smf[E_GATE + row0 + 24];
        const int eg0 = unit * 32 + grp;
        const int tg0 = smi[E_TGT + row0];
        const int tg1 = smi[E_TGT + row0 + 8];
        const int tg2 = smi[E_TGT + row0 + 16];
        const int tg3 = smi[E_TGT + row0 + 24];

        // ---- GEMM2 + scatter gate*(m+be2) ----
#pragma unroll
        for (int nt = 0; nt < 8; nt++) {
            float c0[4] = {0.f, 0.f, 0.f, 0.f};
            float c1[4] = {0.f, 0.f, 0.f, 0.f};
            const int base = nt * 8 * WSTR + bq;
#pragma unroll
            for (int kt = 0; kt < 8; kt++) {
                int o = base + kt * 8;
                uint32_t b0 = smw[E_W2 + o], b1 = smw[E_W2 + o + 4];
                MMA_BF16(c0, a2h[kt*8+0], a2h[kt*8+1], a2h[kt*8+2], a2h[kt*8+3], b0, b1);
                MMA_BF16(c1, a2h[kt*8+4], a2h[kt*8+5], a2h[kt*8+6], a2h[kt*8+7], b0, b1);
            }
            const int n0 = nt * 8 + 2 * qid;
            const float b0v = smf[E_BE2 + n0], b1v = smf[E_BE2 + n0 + 1];
            if (eg0 < E) {
                atomicAdd(g_magg + (size_t)tg0 * 64 + n0,     g0 * (c0[0] + b0v));
                atomicAdd(g_magg + (size_t)tg0 * 64 + n0 + 1, g0 * (c0[1] + b1v));
            }
            if (eg0 + 8 < E) {
                atomicAdd(g_magg + (size_t)tg1 * 64 + n0,     g1 * (c0[2] + b0v));
                atomicAdd(g_magg + (size_t)tg1 * 64 + n0 + 1, g1 * (c0[3] + b1v));
            }
            if (eg0 + 16 < E) {
                atomicAdd(g_magg + (size_t)tg2 * 64 + n0,     g2 * (c1[0] + b0v));
                atomicAdd(g_magg + (size_t)tg2 * 64 + n0 + 1, g2 * (c1[1] + b1v));
            }
            if (eg0 + 24 < E) {
                atomicAdd(g_magg + (size_t)tg3 * 64 + n0,     g3 * (c1[2] + b0v));
                atomicAdd(g_magg + (size_t)tg3 * 64 + n0 + 1, g3 * (c1[3] + b1v));
            }
        }
        __syncwarp();   // protect ACT rows before next unit's gather
    }
}

// ===========================================================================
// NODE kernel: MMA 3-term (precision-critical) — unchanged
// ===========================================================================
#define N_W1_HI 0
#define N_W1_LO 8704
#define N_W2_HI 17408
#define N_W2_LO 21760
#define N_ACT_H 26112
#define N_ACT_L 35840
#define N_BN1   45568
#define N_WS    45696
#define N_WORDS 45760
#define N_BYTES (N_WORDS * 4)

__global__ void __launch_bounds__(256, 1)
node_mma_kernel(const float* __restrict__ z_h,
                const float* __restrict__ Wn1, const float* __restrict__ bn1,
                const float* __restrict__ Wn2, const float* __restrict__ bn2,
                float* __restrict__ out, int N) {
    extern __shared__ uint32_t smw[];
    float* smf = (float*)smw;
    uint16_t* smh = (uint16_t*)smw;

    const int t = threadIdx.x;
    const int w = t >> 5;
    const int l = t & 31;
    const int grp = l >> 2;
    const int qid = l & 3;

    for (int idx = t; idx < 128 * 128; idx += 256) {
        int k = idx >> 7, n = idx & 127;
        float v = Wn1[idx];
        __nv_bfloat16 h = __float2bfloat16(v);
        float r = v - __bfloat162float(h);
        smh[(N_W1_HI + n * WSTR) * 2 + k] = __bfloat16_as_ushort(h);
        smh[(N_W1_LO + n * WSTR) * 2 + k] = __bfloat16_as_ushort(__float2bfloat16(r));
    }
    for (int idx = t; idx < 128 * 64; idx += 256) {
        int k = idx >> 6, n = idx & 63;
        float v = Wn2[idx];
        __nv_bfloat16 h = __float2bfloat16(v);
        float r = v - __bfloat162float(h);
        smh[(N_W2_HI + n * WSTR) * 2 + k] = __bfloat16_as_ushort(h);
        smh[(N_W2_LO + n * WSTR) * 2 + k] = __bfloat16_as_ushort(__float2bfloat16(r));
    }
    if (t < 128) smf[N_BN1 + t] = bn1[t];
    if (t < 64) smf[N_WS + t] = g_wsum[t];
    __syncthreads();

    const int ntiles = (N + 127) / 128;
    const int bq = grp * WSTR + qid;

    for (int tile = blockIdx.x; tile < ntiles; tile += gridDim.x) {
        {
            int e = t >> 1, half = t & 1;
            int n = tile * 128 + e;
            bool v = (n < N);
            const float4* srcp = half
                ? (const float4*)(g_magg + (size_t)(v ? n : 0) * 64)
                : (const float4*)(z_h + (size_t)(v ? n : 0) * 64);
            const float4* wsp = (const float4*)(smf + N_WS);
            uint32_t* rh = smw + N_ACT_H + e * ASTR + half * 32;
            uint32_t* rl = smw + N_ACT_L + e * ASTR + half * 32;
#pragma unroll
            for (int q = 0; q < 16; q++) {
                float4 x = srcp[q];
                if (half) {
                    float4 ws = wsp[q];
                    x.x += ws.x; x.y += ws.y; x.z += ws.z; x.w += ws.w;
                }
                if (!v) x = make_float4(0.f, 0.f, 0.f, 0.f);
                uint32_t h0, l0, h1, l1;
                pack_pair(x.x, x.y, h0, l0);
                pack_pair(x.z, x.w, h1, l1);
                rh[2 * q] = h0; rh[2 * q + 1] = h1;
                rl[2 * q] = l0; rl[2 * q + 1] = l1;
            }
        }
        __syncthreads();

        uint32_t a1h[32], a1l[32];
        {
            const int r0w = (w * 16 + grp) * ASTR + qid;
#pragma unroll
            for (int kt = 0; kt < 8; kt++) {
                int b0 = r0w + kt * 8;
                a1h[kt * 4 + 0] = smw[N_ACT_H + b0];
                a1h[kt * 4 + 1] = smw[N_ACT_H + b0 + 8 * ASTR];
                a1h[kt * 4 + 2] = smw[N_ACT_H + b0 + 4];
                a1h[kt * 4 + 3] = smw[N_ACT_H + b0 + 8 * ASTR + 4];
                a1l[kt * 4 + 0] = smw[N_ACT_L + b0];
                a1l[kt * 4 + 1] = smw[N_ACT_L + b0 + 8 * ASTR];
                a1l[kt * 4 + 2] = smw[N_ACT_L + b0 + 4];
                a1l[kt * 4 + 3] = smw[N_ACT_L + b0 + 8 * ASTR + 4];
            }
        }
        __syncthreads();

        const int rowbase = (w * 16 + grp) * ASTR;

#pragma unroll
        for (int nt = 0; nt < 16; nt++) {
            float c[4] = {0.f, 0.f, 0.f, 0.f};
            const int base = nt * 8 * WSTR + bq;
#pragma unroll
            for (int kt = 0; kt < 8; kt++) {
                int o = base + kt * 8;
                uint32_t bh0 = smw[N_W1_HI + o], bh1 = smw[N_W1_HI + o + 4];
                uint32_t bl0 = smw[N_W1_LO + o], bl1 = smw[N_W1_LO + o + 4];
                MMA_BF16(c, a1h[kt*4], a1h[kt*4+1], a1h[kt*4+2], a1h[kt*4+3], bh0, bh1);
                MMA_BF16(c, a1l[kt*4], a1l[kt*4+1], a1l[kt*4+2], a1l[kt*4+3], bh0, bh1);
                MMA_BF16(c, a1h[kt*4], a1h[kt*4+1], a1h[kt*4+2], a1h[kt*4+3], bl0, bl1);
            }
            int n0 = nt * 8 + 2 * qid;
            float v0 = fmaxf(c[0] + smf[N_BN1 + n0], 0.f);
            float v1 = fmaxf(c[1] + smf[N_BN1 + n0 + 1], 0.f);
            float v2 = fmaxf(c[2] + smf[N_BN1 + n0], 0.f);
            float v3 = fmaxf(c[3] + smf[N_BN1 + n0 + 1], 0.f);
            uint32_t h0, l0, h1, l1;
            pack_pair(v0, v1, h0, l0);
            pack_pair(v2, v3, h1, l1);
            int wi = rowbase + nt * 4 + qid;
            smw[N_ACT_H + wi] = h0;
            smw[N_ACT_L + wi] = l0;
            smw[N_ACT_H + wi + 8 * ASTR] = h1;
            smw[N_ACT_L + wi + 8 * ASTR] = l1;
        }

        uint32_t a2h[32], a2l[32];
        {
            const int r0w = rowbase + qid;
#pragma unroll
            for (int kt = 0; kt < 8; kt++) {
                int b0 = r0w + kt * 8;
                a2h[kt * 4 + 0] = smw[N_ACT_H + b0];
                a2h[kt * 4 + 1] = smw[N_ACT_H + b0 + 8 * ASTR];
                a2h[kt * 4 + 2] = smw[N_ACT_H + b0 + 4];
                a2h[kt * 4 + 3] = smw[N_ACT_H + b0 + 8 * ASTR + 4];
                a2l[kt * 4 + 0] = smw[N_ACT_L + b0];
                a2l[kt * 4 + 1] = smw[N_ACT_L + b0 + 8 * ASTR];
                a2l[kt * 4 + 2] = smw[N_ACT_L + b0 + 4];
                a2l[kt * 4 + 3] = smw[N_ACT_L + b0 + 8 * ASTR + 4];
            }
        }
        const int r0 = tile * 128 + w * 16 + grp;
        const int r1 = r0 + 8;

#pragma unroll
        for (int nt = 0; nt < 8; nt++) {
            float c[4] = {0.f, 0.f, 0.f, 0.f};
            const int base = nt * 8 * WSTR + bq;
#pragma unroll
            for (int kt = 0; kt < 8; kt++) {
                int o = base + kt * 8;
                uint32_t bh0 = smw[N_W2_HI + o], bh1 = smw[N_W2_HI + o + 4];
                uint32_t bl0 = smw[N_W2_LO + o], bl1 = smw[N_W2_LO + o + 4];
                MMA_BF16(c, a2h[kt*4], a2h[kt*4+1], a2h[kt*4+2], a2h[kt*4+3], bh0, bh1);
                MMA_BF16(c, a2l[kt*4], a2l[kt*4+1], a2l[kt*4+2], a2l[kt*4+3], bh0, bh1);
                MMA_BF16(c, a2h[kt*4], a2h[kt*4+1], a2h[kt*4+2], a2h[kt*4+3], bl0, bl1);
            }
            int n0 = nt * 8 + 2 * qid;
            float b0v = __ldg(&bn2[n0]), b1v = __ldg(&bn2[n0 + 1]);
            if (r0 < N) {
                float2 o2 = make_float2(c[0] + b0v, c[1] + b1v);
                *(float2*)(out + (size_t)r0 * 64 + n0) = o2;
            }
            if (r1 < N) {
                float2 o2 = make_float2(c[2] + b0v, c[3] + b1v);
                *(float2*)(out + (size_t)r1 * 64 + n0) = o2;
            }
        }
        __syncthreads();
    }
}

// ===========================================================================
// WORLD kernel: MMA 3-term — unchanged
// ===========================================================================
#define W_W1_HI 0
#define W_W1_LO 8704
#define W_W2_HI 17408
#define W_W2_LO 21760
#define W_ACT_H 26112
#define W_ACT_L 35840
#define W_BW1   45568
#define W_RED   45696
#define W_WORDS 46208
#define W_BYTES (W_WORDS * 4)

__global__ void __launch_bounds__(256, 1)
world_mma_kernel(const float* __restrict__ z_h, const float* __restrict__ pos_world,
                 const float* __restrict__ Ww1, const float* __restrict__ bw1,
                 const float* __restrict__ Ww2, int N) {
    extern __shared__ uint32_t smw[];
    float* smf = (float*)smw;
    uint16_t* smh = (uint16_t*)smw;

    const int t = threadIdx.x;
    const int w = t >> 5;
    const int l = t & 31;
    const int grp = l >> 2;
    const int qid = l & 3;

    for (int i = t; i < 17408; i += 256) smw[W_W1_HI + i] = 0;
    __syncthreads();
    for (int idx = t; idx < 67 * 128; idx += 256) {
        int k = idx >> 7, n = idx & 127;
        float v = Ww1[idx];
        __nv_bfloat16 h = __float2bfloat16(v);
        float r = v - __bfloat162float(h);
        smh[(W_W1_HI + n * WSTR) * 2 + k] = __bfloat16_as_ushort(h);
        smh[(W_W1_LO + n * WSTR) * 2 + k] = __bfloat16_as_ushort(__float2bfloat16(r));
    }
    for (int idx = t; idx < 128 * 64; idx += 256) {
        int k = idx >> 6, n = idx & 63;
        float v = Ww2[idx];
        __nv_bfloat16 h = __float2bfloat16(v);
        float r = v - __bfloat162float(h);
        smh[(W_W2_HI + n * WSTR) * 2 + k] = __bfloat16_as_ushort(h);
        smh[(W_W2_LO + n * WSTR) * 2 + k] = __bfloat16_as_ushort(__float2bfloat16(r));
    }
    if (t < 128) smf[W_BW1 + t] = bw1[t];
    const float p0 = __ldg(&pos_world[0]);
    const float p1 = __ldg(&pos_world[1]);
    const float p2 = __ldg(&pos_world[2]);
    __syncthreads();

    const int ntiles = (N + 127) / 128;
    const int bq = grp * WSTR + qid;

    float accs[16];
#pragma unroll
    for (int i = 0; i < 16; i++) accs[i] = 0.f;

    for (int tile = blockIdx.x; tile < ntiles; tile += gridDim.x) {
        {
            int e = t >> 1, half = t & 1;
            int n = tile * 128 + e;
            bool v = (n < N);
            const float4* zp = (const float4*)(z_h + (size_t)(v ? n : 0) * 64) + half * 8;
            uint32_t* rh = smw + W_ACT_H + e * ASTR + half * 16;
            uint32_t* rl = smw + W_ACT_L + e * ASTR + half * 16;
#pragma unroll
            for (int q = 0; q < 8; q++) {
                float4 x = zp[q];
                if (!v) x = make_float4(0.f, 0.f, 0.f, 0.f);
                uint32_t h0, l0, h1, l1;
                pack_pair(x.x, x.y, h0, l0);
                pack_pair(x.z, x.w, h1, l1);
                rh[2 * q] = h0; rh[2 * q + 1] = h1;
                rl[2 * q] = l0; rl[2 * q + 1] = l1;
            }
        }
        if (t < 128) {
            int n = tile * 128 + t;
            bool v = (n < N);
            float4 z0 = *(const float4*)(z_h + (size_t)(v ? n : 0) * 64);
            float d0 = v ? z0.x - p0 : 0.f;
            float d1 = v ? z0.y - p1 : 0.f;
            float d2 = v ? z0.z - p2 : 0.f;
            uint32_t* rh = smw + W_ACT_H + t * ASTR + 32;
            uint32_t* rl = smw + W_ACT_L + t * ASTR + 32;
            uint32_t h0, l0, h1, l1;
            pack_pair(d0, d1, h0, l0);
            pack_pair(d2, 0.f, h1, l1);
            rh[0] = h0; rl[0] = l0;
            rh[1] = h1; rl[1] = l1;
#pragma unroll
            for (int q = 2; q < 8; q++) { rh[q] = 0; rl[q] = 0; }
        }
        __syncthreads();

        uint32_t a1h[20], a1l[20];
        {
            const int r0w = (w * 16 + grp) * ASTR + qid;
#pragma unroll
            for (int kt = 0; kt < 5; kt++) {
                int b0 = r0w + kt * 8;
                a1h[kt * 4 + 0] = smw[W_ACT_H + b0];
                a1h[kt * 4 + 1] = smw[W_ACT_H + b0 + 8 * ASTR];
                a1h[kt * 4 + 2] = smw[W_ACT_H + b0 + 4];
                a1h[kt * 4 + 3] = smw[W_ACT_H + b0 + 8 * ASTR + 4];
                a1l[kt * 4 + 0] = smw[W_ACT_L + b0];
                a1l[kt * 4 + 1] = smw[W_ACT_L + b0 + 8 * ASTR];
                a1l[kt * 4 + 2] = smw[W_ACT_L + b0 + 4];
                a1l[kt * 4 + 3] = smw[W_ACT_L + b0 + 8 * ASTR + 4];
            }
        }
        __syncthreads();

        const int rowbase = (w * 16 + grp) * ASTR;

#pragma unroll
        for (int nt = 0; nt < 16; nt++) {
            float c[4] = {0.f, 0.f, 0.f, 0.f};
            const int base = nt * 8 * WSTR + bq;
#pragma unroll
            for (int kt = 0; kt < 5; kt++) {
                int o = base + kt * 8;
                uint32_t bh0 = smw[W_W1_HI + o], bh1 = smw[W_W1_HI + o + 4];
                uint32_t bl0 = smw[W_W1_LO + o], bl1 = smw[W_W1_LO + o + 4];
                MMA_BF16(c, a1h[kt*4], a1h[kt*4+1], a1h[kt*4+2], a1h[kt*4+3], bh0, bh1);
                MMA_BF16(c, a1l[kt*4], a1l[kt*4+1], a1l[kt*4+2], a1l[kt*4+3], bh0, bh1);
                MMA_BF16(c, a1h[kt*4], a1h[kt*4+1], a1h[kt*4+2], a1h[kt*4+3], bl0, bl1);
            }
            int n0 = nt * 8 + 2 * qid;
            float v0 = fmaxf(c[0] + smf[W_BW1 + n0], 0.f);
            float v1 = fmaxf(c[1] + smf[W_BW1 + n0 + 1], 0.f);
            float v2 = fmaxf(c[2] + smf[W_BW1 + n0], 0.f);
            float v3 = fmaxf(c[3] + smf[W_BW1 + n0 + 1], 0.f);
            uint32_t h0, l0, h1, l1;
            pack_pair(v0, v1, h0, l0);
            pack_pair(v2, v3, h1, l1);
            int wi = rowbase + nt * 4 + qid;
            smw[W_ACT_H + wi] = h0;
            smw[W_ACT_L + wi] = l0;
            smw[W_ACT_H + wi + 8 * ASTR] = h1;
            smw[W_ACT_L + wi + 8 * ASTR] = l1;
        }

        uint32_t a2h[32], a2l[32];
        {
            const int r0w = rowbase + qid;
#pragma unroll
            for (int kt = 0; kt < 8; kt++) {
                int b0 = r0w + kt * 8;
                a2h[kt * 4 + 0] = smw[W_ACT_H + b0];
                a2h[kt * 4 + 1] = smw[W_ACT_H + b0 + 8 * ASTR];
                a2h[kt * 4 + 2] = smw[W_ACT_H + b0 + 4];
                a2h[kt * 4 + 3] = smw[W_ACT_H + b0 + 8 * ASTR + 4];
                a2l[kt * 4 + 0] = smw[W_ACT_L + b0];
                a2l[kt * 4 + 1] = smw[W_ACT_L + b0 + 8 * ASTR];
                a2l[kt * 4 + 2] = smw[W_ACT_L + b0 + 4];
                a2l[kt * 4 + 3] = smw[W_ACT_L + b0 + 8 * ASTR + 4];
            }
        }
        const int r0 = tile * 128 + w * 16 + grp;
        const float m0 = (r0 < N) ? 1.f : 0.f;
        const float m1 = (r0 + 8 < N) ? 1.f : 0.f;

#pragma unroll
        for (int nt = 0; nt < 8; nt++) {
            float c[4] = {0.f, 0.f, 0.f, 0.f};
            const int base = nt * 8 * WSTR + bq;
#pragma unroll
            for (int kt = 0; kt < 8; kt++) {
                int o = base + kt * 8;
                uint32_t bh0 = smw[W_W2_HI + o], bh1 = smw[W_W2_HI + o + 4];
                uint32_t bl0 = smw[W_W2_LO + o], bl1 = smw[W_W2_LO + o + 4];
                MMA_BF16(c, a2h[kt*4], a2h[kt*4+1], a2h[kt*4+2], a2h[kt*4+3], bh0, bh1);
                MMA_BF16(c, a2l[kt*4], a2l[kt*4+1], a2l[kt*4+2], a2l[kt*4+3], bh0, bh1);
                MMA_BF16(c, a2h[kt*4], a2h[kt*4+1], a2h[kt*4+2], a2h[kt*4+3], bl0, bl1);
            }
            accs[nt * 2]     += m0 * c[0] + m1 * c[2];
            accs[nt * 2 + 1] += m0 * c[1] + m1 * c[3];
        }
        __syncthreads();
    }

#pragma unroll
    for (int i = 0; i < 16; i++) {
        accs[i] += __shfl_xor_sync(0xffffffffu, accs[i], 4);
        accs[i] += __shfl_xor_sync(0xffffffffu, accs[i], 8);
        accs[i] += __shfl_xor_sync(0xffffffffu, accs[i], 16);
    }
    if (l < 4) {
#pragma unroll
        for (int nt = 0; nt < 8; nt++) {
            smf[W_RED + w * 64 + nt * 8 + 2 * l]     = accs[nt * 2];
            smf[W_RED + w * 64 + nt * 8 + 2 * l + 1] = accs[nt * 2 + 1];
        }
    }
    __syncthreads();
    if (t < 64) {
        float s = 0.f;
#pragma unroll
        for (int ww = 0; ww < 8; ww++) s += smf[W_RED + ww * 64 + t];
        atomicAdd(&g_wsum[t], s);
    }
}

// ===========================================================================
extern "C" void kernel_launch(void* const* d_in, const int* in_sizes, int n_in,
                              void* d_out, int out_size) {
    const float* z_h       = (const float*)d_in[0];
    const float* pos_world = (const float*)d_in[1];
    const int*   ei        = (const int*)d_in[2];
    const float* We1 = (const float*)d_in[3];
    const float* be1 = (const float*)d_in[4];
    const float* We2 = (const float*)d_in[5];
    const float* be2 = (const float*)d_in[6];
    const float* Wg1 = (const float*)d_in[7];
    const float* bg1 = (const float*)d_in[8];
    const float* Wg2 = (const float*)d_in[9];
    const float* bg2 = (const float*)d_in[10];
    const float* Wn1 = (const float*)d_in[11];
    const float* bn1 = (const float*)d_in[12];
    const float* Wn2 = (const float*)d_in[13];
    const float* bn2 = (const float*)d_in[14];
    const float* Ww1 = (const float*)d_in[15];
    const float* bw1 = (const float*)d_in[16];
    const float* Ww2 = (const float*)d_in[17];
    const float* bw2 = (const float*)d_in[18];

    const int N = in_sizes[0] / 64;
    const int E = in_sizes[2] / 2;
    float* out = (float*)d_out;

    cudaFuncSetAttribute(edge_mma_kernel,
                         cudaFuncAttributeMaxDynamicSharedMemorySize, E_BYTES);
    cudaFuncSetAttribute(node_mma_kernel,
                         cudaFuncAttributeMaxDynamicSharedMemorySize, N_BYTES);
    cudaFuncSetAttribute(world_mma_kernel,
                         cudaFuncAttributeMaxDynamicSharedMemorySize, W_BYTES);

    const int total = N * 64;
    zero_kernel<<<(total + 255) / 256, 256>>>(total, bw2, (float)N);
    prepack_kernel<<<(N * 32 + 255) / 256, 256>>>(z_h, N * 32);
    world_mma_kernel<<<148, 256, W_BYTES>>>(z_h, pos_world, Ww1, bw1, Ww2, N);
    edge_mma_kernel<<<148, ETHREADS, E_BYTES>>>(ei, We1, be1, We2, be2,
                                                Wg1, bg1, Wg2, bg2, E);
    node_mma_kernel<<<148, 256, N_BYTES>>>(z_h, Wn1, bn1, Wn2, bn2, out, N);
}